// round 13
// baseline (speedup 1.0000x reference)
#include <cuda_runtime.h>
#include <cuda_fp16.h>
#include <math.h>
#include <stdint.h>

#define NB      512
#define CHUNK   257
#define NCOEF   771
#define NFRAMES 128
#define NSAMP   32768

#define KSEG    1056            // A cols (multiple of 32, minimal padding)
#define AK      KSEG
#define BROWS   KSEG            // B rows (single fp16 segment)
#define MROWS   (NB*NFRAMES)    // 65536
#define NCHUNK  33              // 1056 / 32
#define NSEGQ   8
#define FSEG    (NFRAMES/NSEGQ)
#define NSPLIT  8
#define ISEG    64
#define NBASIS  33              // basis CTAs (1056 / 32 rows)
#define NTILES  1024            // 512 batches x 2 N-halves
#define NPCTA   304             // persistent CTAs (2 per SM x 152)
// Per-row fp16 layout (1056 cols): [0,514) current, [514,520) zero,
// [520,1034) shifted (16B-aligned), [1034,1056) zero.

__device__ __half    g_A[(size_t)MROWS * AK];    // ~138.4 MB
__device__ __half    g_B[(size_t)BROWS * 256];   // ~0.54 MB
__device__ float     g_part[NSPLIT * NB * CHUNK * 3];
__device__ float4    g_par[NB * CHUNK];
__device__ float     g_ss[NB];
__device__ unsigned  g_cnt[NB];

// ---------------------------------------------------------------------------
// kP1a: split-K selection GEMM partials, grid (64, NSPLIT+1).
// blockIdx.y == NSPLIT rows build the DFT basis (kBasis folded in).
// ---------------------------------------------------------------------------
#define BPB 8
__global__ void __launch_bounds__(288) kP1a(const float* __restrict__ sel,
                                            const float* __restrict__ items) {
    const int tid = threadIdx.x;

    if (blockIdx.y == NSPLIT) {
        // ---- basis blocks: B[1056][256], Hann folded, fp16 ----
        __shared__ float2 tw[512];
        if (blockIdx.x >= NBASIS) return;
        if (tid < 256) {
            float sn, cs;
            sincosf((float)tid * (6.283185307179586f / 512.f), &sn, &cs);
            tw[tid] = make_float2(cs, sn);
            sincosf((float)(tid + 256) * (6.283185307179586f / 512.f), &sn, &cs);
            tw[tid + 256] = make_float2(cs, sn);
        }
        __syncthreads();
        if (tid < 256) {
            const int n = tid;
            const float h1 = 0.5f - 0.5f * cosf((float)n         * (6.283185307179586f / 511.f));
            const float h2 = 0.5f - 0.5f * cosf((float)(n + 256) * (6.283185307179586f / 511.f));
#pragma unroll 1
            for (int ri = 0; ri < 32; ri++) {
                const int rr = blockIdx.x * 32 + ri;      // 0..1055
                float v = 0.f;
                if (rr < 514) {
                    const int k = rr >> 1, odd = rr & 1;
                    const float2 t = tw[(k * n) & 511];
                    v = (odd ? -t.y : t.x) * h1;
                } else if (rr >= 520 && rr < 1034) {
                    const int k = (rr - 520) >> 1, odd = (rr - 520) & 1;
                    const float2 t = tw[(k * n) & 511];
                    v = (odd ? -t.y : t.x) * h2;
                }
                g_B[(size_t)rr * 256 + n] = __float2half_rn(v);
            }
        }
        return;
    }

    // ---- split-K partial GEMM ----
    __shared__ float sh_sel[BPB * ISEG];
    const int b0  = blockIdx.x * BPB;
    const int sp  = blockIdx.y;
    const int i0  = sp * ISEG;

    for (int idx = tid; idx < BPB * ISEG; idx += 288) {
        const int b = idx / ISEG, ii = idx % ISEG;
        const float v = sel[(b0 + b) * 512 + i0 + ii];
        sh_sel[idx] = v > 0.f ? v : 0.f;
    }
    __syncthreads();

    const int k = tid;
    if (k >= CHUNK) return;

    float am[BPB], ap[BPB], as_[BPB];
#pragma unroll
    for (int b = 0; b < BPB; b++) { am[b] = 0.f; ap[b] = 0.f; as_[b] = 0.f; }

    for (int ii = 0; ii < ISEG; ii++) {
        const int i = i0 + ii;
        const float i0v = items[i * NCOEF + k];
        const float i1v = items[i * NCOEF + CHUNK + k];
        const float i2v = items[i * NCOEF + 2 * CHUNK + k];
#pragma unroll
        for (int b = 0; b < BPB; b++) {
            const float s = sh_sel[b * ISEG + ii];
            am[b]  = fmaf(s, i0v, am[b]);
            ap[b]  = fmaf(s, i1v, ap[b]);
            as_[b] = fmaf(s, i2v, as_[b]);
        }
    }
#pragma unroll
    for (int b = 0; b < BPB; b++) {
        float* p = &g_part[(size_t)(((sp * NB) + b0 + b) * CHUNK + k) * 3];
        p[0] = am[b]; p[1] = ap[b]; p[2] = as_[b];
    }
}

// ---------------------------------------------------------------------------
// kP1b: fixed-order combine + activations -> per-(b,k) rotator params.
// Also resets g_ss / g_cnt for this launch.
// ---------------------------------------------------------------------------
__global__ void __launch_bounds__(288) kP1b() {
    const int b = blockIdx.x;
    const int k = threadIdx.x;
    if (k == 280) g_ss[b] = 0.f;
    if (k == 281) g_cnt[b] = 0u;
    if (k >= CHUNK) return;

    float am = 0.f, ap = 0.f, as_ = 0.f;
#pragma unroll
    for (int sp = 0; sp < NSPLIT; sp++) {
        const float* p = &g_part[(size_t)(((sp * NB) + b) * CHUNK + k) * 3];
        am += p[0]; ap += p[1]; as_ += p[2];
    }

    const float w = (k == 0 || k == 256) ? (1.f / 512.f) : (2.f / 512.f);
    const float m  = fmaf(1.f / (1.f + expf(-am)), 0.9999f * 0.5f, 0.5f);
    const float ph = tanhf(ap) * 3.14159265358979323846f;
    const float st = 1.f / (1.f + expf(-as_));
    float sn, cs;
    sincosf(ph, &sn, &cs);
    const float rRe = m * cs, rIm = m * sn;
    const float ws  = w * st;
    g_par[b * CHUNK + k] = make_float4(rRe, rIm, ws * rRe, ws * rIm);
}

// ---------------------------------------------------------------------------
// kP2: segment-parallel rotator recurrence -> fp16 A, 128-bit stores.
// t<64: bins 4t..4t+3.  t==64: bin 256.  t in [65,79): pad zeroing.
// ---------------------------------------------------------------------------
__device__ __forceinline__ float2 cmul(float2 a, float2 b) {
    return make_float2(fmaf(a.x, b.x, -(a.y * b.y)), fmaf(a.x, b.y, a.y * b.x));
}
__device__ __forceinline__ float2 csq(float2 a) {
    return make_float2(fmaf(a.x, a.x, -(a.y * a.y)), 2.f * a.x * a.y);
}
__device__ __forceinline__ unsigned int pack_h2(float2 c) {
    const __half2 h = __floats2half2_rn(c.x, c.y);
    return *(const unsigned int*)&h;
}

__global__ void __launch_bounds__(96) kP2() {
    const int t = threadIdx.x;
    const int b = blockIdx.x;
    const int s = blockIdx.y;
    char* Ab = (char*)g_A;
    const size_t rowStride = (size_t)AK * 2;              // 2112 B
    const size_t base = (size_t)b * NFRAMES * rowStride;

    if (t < 64) {
        float2 r[4], c[4];
#pragma unroll
        for (int j = 0; j < 4; j++) {
            const float4 p = g_par[b * CHUNK + 4 * t + j];
            r[j] = make_float2(p.x, p.y);
            c[j] = make_float2(p.z, p.w);
        }
#pragma unroll
        for (int j = 0; j < 4; j++) {
            float2 tt = csq(csq(csq(csq(r[j]))));   // r^16
            if (s & 1) c[j] = cmul(c[j], tt);
            tt = csq(tt);
            if (s & 2) c[j] = cmul(c[j], tt);
            tt = csq(tt);
            if (s & 4) c[j] = cmul(c[j], tt);
        }
        const unsigned long long sgn = 0x8000800000000000ULL;  // odd bin in hi u32
        if (s == 0) {   // frame 0 has no previous frame
            *(ulonglong2*)(Ab + base + 1040 + 16 * t) = make_ulonglong2(0, 0);
        }
#pragma unroll 1
        for (int i = 0; i < FSEG; i++) {
            const int f = s * FSEG + i;
            const unsigned long long h01 =
                (unsigned long long)pack_h2(c[0]) | ((unsigned long long)pack_h2(c[1]) << 32);
            const unsigned long long h23 =
                (unsigned long long)pack_h2(c[2]) | ((unsigned long long)pack_h2(c[3]) << 32);

            char* rp = Ab + base + (size_t)f * rowStride;
            *(ulonglong2*)(rp + 16 * t) = make_ulonglong2(h01, h23);
            if (f + 1 < NFRAMES) {
                *(ulonglong2*)(rp + rowStride + 1040 + 16 * t) =
                    make_ulonglong2(h01 ^ sgn, h23 ^ sgn);
            }
#pragma unroll
            for (int j = 0; j < 4; j++) c[j] = cmul(c[j], r[j]);
        }
    } else if (t == 64) {
        // bin 256 (even k -> no sign flip)
        const float4 p = g_par[b * CHUNK + 256];
        const float2 r = make_float2(p.x, p.y);
        float2 c = make_float2(p.z, p.w);
        float2 tt = csq(csq(csq(csq(r))));
        if (s & 1) c = cmul(c, tt);
        tt = csq(tt);
        if (s & 2) c = cmul(c, tt);
        tt = csq(tt);
        if (s & 4) c = cmul(c, tt);
        if (s == 0) *(unsigned int*)(Ab + base + 2064) = 0u;
#pragma unroll 1
        for (int i = 0; i < FSEG; i++) {
            const int f = s * FSEG + i;
            const unsigned int hu = pack_h2(c);
            char* rp = Ab + base + (size_t)f * rowStride;
            *(unsigned int*)(rp + 1024) = hu;
            if (f + 1 < NFRAMES)
                *(unsigned int*)(rp + rowStride + 2064) = hu;
            c = cmul(c, r);
        }
    } else if (t < 79) {
        // pads: u32 idx 257..259 (cols 514..519) and 517..527 (cols 1034..1055)
        const int q = t - 65;              // 0..13
        const unsigned off = (q < 3) ? (257u + q) : (517u + (q - 3));
        unsigned int* pA32 = (unsigned int*)g_A;
#pragma unroll 1
        for (int i = 0; i < FSEG; i++) {
            const size_t rw32 = ((size_t)(b * NFRAMES + s * FSEG + i) * AK) >> 1;
            pA32[rw32 + off] = 0u;
        }
    }
}

// ---------------------------------------------------------------------------
// kG: persistent fp16 mma.sync GEMM. 304 CTAs walk tiles bid, bid+304, ...
// (tile t: batch = t>>1, N-half = t&1). The cp.async prefetch stream runs
// 4 chunk-groups ahead ACROSS tile boundaries, hiding each tile's prologue
// and epilogue. Mainloop body identical to the proven BK=32/5-stage config.
// Fused L2 normalization: second CTA of each batch to finish rescales its
// own half from registers + partner half from global.
// ---------------------------------------------------------------------------
#define LDA_S 40
#define LDB_S 136
#define AS_BYTES (128 * LDA_S * 2)
#define BS_BYTES (32 * LDB_S * 2)
#define NSTAGE   5
#define SMEM_KG  (NSTAGE * (AS_BYTES + BS_BYTES))

__device__ __forceinline__ void cpa16(unsigned int s, const void* g) {
    asm volatile("cp.async.cg.shared.global [%0],[%1],16;" :: "r"(s), "l"(g));
}
__device__ __forceinline__ void ldm4(unsigned int& r0, unsigned int& r1,
                                     unsigned int& r2, unsigned int& r3, unsigned int a) {
    asm volatile("ldmatrix.sync.aligned.m8n8.x4.shared.b16 {%0,%1,%2,%3},[%4];"
                 : "=r"(r0), "=r"(r1), "=r"(r2), "=r"(r3) : "r"(a));
}
__device__ __forceinline__ void ldm4t(unsigned int& r0, unsigned int& r1,
                                      unsigned int& r2, unsigned int& r3, unsigned int a) {
    asm volatile("ldmatrix.sync.aligned.m8n8.x4.trans.shared.b16 {%0,%1,%2,%3},[%4];"
                 : "=r"(r0), "=r"(r1), "=r"(r2), "=r"(r3) : "r"(a));
}
__device__ __forceinline__ void mma16816(float* c, const unsigned int* a, const unsigned int* b) {
    asm volatile("mma.sync.aligned.m16n8k16.row.col.f32.f16.f16.f32 "
                 "{%0,%1,%2,%3},{%4,%5,%6,%7},{%8,%9},{%0,%1,%2,%3};"
                 : "+f"(c[0]), "+f"(c[1]), "+f"(c[2]), "+f"(c[3])
                 : "r"(a[0]), "r"(a[1]), "r"(a[2]), "r"(a[3]), "r"(b[0]), "r"(b[1]));
}

__global__ void __launch_bounds__(256, 2) kG(float* __restrict__ out) {
    extern __shared__ __align__(16) __half dsm[];
    __shared__ float red[8];
    __shared__ unsigned s_flag;
    __shared__ float s_inv;

    const int tid   = threadIdx.x;
    const int lane  = tid & 31;
    const int wid   = tid >> 5;
    const int warpM = wid >> 2;
    const int warpN = wid & 3;
    const int bid   = blockIdx.x;

    const unsigned int base = (unsigned int)__cvta_generic_to_shared(dsm);
#define SA_STAGE(i) (base + (unsigned)(i) * AS_BYTES)
#define SB_STAGE(i) (base + (unsigned)NSTAGE * AS_BYTES + (unsigned)(i) * BS_BYTES)

    const int aRow = tid >> 2, aOff = (tid & 3) * 8;
    const int bRow = tid >> 4, bOff = (tid & 15) * 8;

    const __half* A = g_A;
    const __half* B = g_B;

    const int lrow  = (lane & 7) + ((lane >> 3) & 1) * 8;
    const int lcol8 = (lane >> 4) * 8;

    // PREFETCH: chunk cIdx of tile tt into stage st.
#define PREFETCH(tt, cIdx, st)                                                        \
    {                                                                                 \
        const int pm = ((tt) >> 1) * 128;                                             \
        const int pn = ((tt) & 1) * 128;                                              \
        const int aCol = (cIdx) * 32;                                                 \
        const int bR   = (cIdx) * 32;                                                 \
        const unsigned int sa = SA_STAGE(st);                                         \
        const unsigned int sb = SB_STAGE(st);                                         \
        cpa16(sa + (unsigned)(aRow * LDA_S + aOff) * 2,                               \
              A + (size_t)(pm + aRow) * AK + aCol + aOff);                            \
        cpa16(sa + (unsigned)((aRow + 64) * LDA_S + aOff) * 2,                        \
              A + (size_t)(pm + aRow + 64) * AK + aCol + aOff);                       \
        cpa16(sb + (unsigned)(bRow * LDB_S + bOff) * 2,                               \
              B + (size_t)(bR + bRow) * 256 + pn + bOff);                             \
        cpa16(sb + (unsigned)((bRow + 16) * LDB_S + bOff) * 2,                        \
              B + (size_t)(bR + bRow + 16) * 256 + pn + bOff);                        \
        asm volatile("cp.async.commit_group;");                                       \
    }

    // Prefetch stream cursor (runs 4 groups ahead, crosses tile boundaries)
    int pf_t = bid, pf_c = 0, pf_stg = 0;
#pragma unroll
    for (int i = 0; i < 4; i++) {
        if (pf_t < NTILES) {
            PREFETCH(pf_t, pf_c, pf_stg)
            if (++pf_c == NCHUNK) { pf_c = 0; pf_t += NPCTA; }
            if (++pf_stg == NSTAGE) pf_stg = 0;
        }
    }

    int stg = 0;
    for (int t = bid; t < NTILES; t += NPCTA) {
        const int mBase = (t >> 1) * 128;
        const int nBase = (t & 1) * 128;

        float c[4][4][4];
#pragma unroll
        for (int i = 0; i < 4; i++)
#pragma unroll
            for (int j = 0; j < 4; j++)
#pragma unroll
                for (int q = 0; q < 4; q++) c[i][j][q] = 0.f;

        for (int ch = 0; ch < NCHUNK; ch++) {
            if (pf_t < NTILES) {
                asm volatile("cp.async.wait_group 3;");
            } else {
                asm volatile("cp.async.wait_group 0;");
            }
            __syncthreads();
            if (pf_t < NTILES) {
                PREFETCH(pf_t, pf_c, pf_stg)
                if (++pf_c == NCHUNK) { pf_c = 0; pf_t += NPCTA; }
                if (++pf_stg == NSTAGE) pf_stg = 0;
            }

            const unsigned int sAcur = SA_STAGE(stg);
            const unsigned int sBcur = SB_STAGE(stg);
#pragma unroll
            for (int kk = 0; kk < 32; kk += 16) {
                unsigned int af[4][4];
#pragma unroll
                for (int mi = 0; mi < 4; mi++) {
                    const unsigned int addr = sAcur +
                        (unsigned)((warpM * 64 + mi * 16 + lrow) * LDA_S + kk + lcol8) * 2;
                    ldm4(af[mi][0], af[mi][1], af[mi][2], af[mi][3], addr);
                }
                unsigned int bf[4][2];
#pragma unroll
                for (int nj = 0; nj < 2; nj++) {
                    const unsigned int addr = sBcur +
                        (unsigned)((kk + lrow) * LDB_S + warpN * 32 + nj * 16 + lcol8) * 2;
                    unsigned int r0, r1, r2, r3;
                    ldm4t(r0, r1, r2, r3, addr);
                    bf[nj * 2][0] = r0; bf[nj * 2][1] = r1;
                    bf[nj * 2 + 1][0] = r2; bf[nj * 2 + 1][1] = r3;
                }
#pragma unroll
                for (int mi = 0; mi < 4; mi++)
#pragma unroll
                    for (int nf = 0; nf < 4; nf++)
                        mma16816(c[mi][nf], af[mi], bf[nf]);
            }
            if (++stg == NSTAGE) stg = 0;
        }

        // ---- epilogue: store unnormalized + partial sum of squares ----
        // (next tile's first chunks are already streaming in via cp.async)
        float ss = 0.f;
#pragma unroll
        for (int mi = 0; mi < 4; mi++) {
#pragma unroll
            for (int nf = 0; nf < 4; nf++) {
                const int r = mBase + warpM * 64 + mi * 16 + (lane >> 2);
                const int n = nBase + warpN * 32 + nf * 8 + (lane & 3) * 2;
                float2* p0 = (float2*)(out + (size_t)r * 256 + n);
                float2* p1 = (float2*)(out + (size_t)(r + 8) * 256 + n);
                *p0 = make_float2(c[mi][nf][0], c[mi][nf][1]);
                *p1 = make_float2(c[mi][nf][2], c[mi][nf][3]);
#pragma unroll
                for (int q = 0; q < 4; q++) ss = fmaf(c[mi][nf][q], c[mi][nf][q], ss);
            }
        }
#pragma unroll
        for (int o = 16; o > 0; o >>= 1) ss += __shfl_xor_sync(0xffffffffu, ss, o);
        if (lane == 0) red[wid] = ss;

        // release: make this tile's stores visible before signaling
        __threadfence();
        __syncthreads();

        if (tid == 0) {
            float tot = 0.f;
#pragma unroll
            for (int i = 0; i < 8; i++) tot += red[i];
            atomicAdd(&g_ss[t >> 1], tot);
            __threadfence();                              // order ss-add before cnt-add
            const unsigned old = atomicAdd(&g_cnt[t >> 1], 1u);
            s_flag = old;                                 // 1 -> we are the finisher
            if (old == 1u) {
                __threadfence();                          // acquire
                s_inv = 1.f / (sqrtf(g_ss[t >> 1]) + 1e-8f);
            }
        }
        __syncthreads();

        if (s_flag == 1u) {
            const float inv = s_inv;
            // own half: rescale from still-live registers (no global re-read)
#pragma unroll
            for (int mi = 0; mi < 4; mi++) {
#pragma unroll
                for (int nf = 0; nf < 4; nf++) {
                    const int r = mBase + warpM * 64 + mi * 16 + (lane >> 2);
                    const int n = nBase + warpN * 32 + nf * 8 + (lane & 3) * 2;
                    float2* p0 = (float2*)(out + (size_t)r * 256 + n);
                    float2* p1 = (float2*)(out + (size_t)(r + 8) * 256 + n);
                    *p0 = make_float2(c[mi][nf][0] * inv, c[mi][nf][1] * inv);
                    *p1 = make_float2(c[mi][nf][2] * inv, c[mi][nf][3] * inv);
                }
            }
            // partner half: read-scale-write (L2-hot)
            const int pbase = nBase ^ 128;
#pragma unroll 4
            for (int i = tid; i < 128 * 32; i += 256) {
                const int row = i >> 5, c4 = i & 31;
                float4* p = (float4*)(out + (size_t)(mBase + row) * 256 + pbase) + c4;
                float4 v = *p;
                v.x *= inv; v.y *= inv; v.z *= inv; v.w *= inv;
                *p = v;
            }
        }
    }
#undef PREFETCH
#undef SA_STAGE
#undef SB_STAGE
}

extern "C" void kernel_launch(void* const* d_in, const int* in_sizes, int n_in,
                              void* d_out, int out_size) {
    const float* sel   = (const float*)d_in[0];
    const float* items = (const float*)d_in[1];
    if (n_in >= 2 && in_sizes[0] == 512 * 771) {
        items = (const float*)d_in[0];
        sel   = (const float*)d_in[1];
    }
    float* out = (float*)d_out;

    static bool attr_set = false;
    if (!attr_set) {
        cudaFuncSetAttribute(kG, cudaFuncAttributeMaxDynamicSharedMemorySize, SMEM_KG);
        attr_set = true;
    }

    kP1a<<<dim3(NB / BPB, NSPLIT + 1), 288>>>(sel, items);
    kP1b<<<NB, 288>>>();
    kP2<<<dim3(NB, NSEGQ), 96>>>();
    kG<<<NPCTA, 256, SMEM_KG>>>(out);
}

// round 14
// speedup vs baseline: 1.0509x; 1.0509x over previous
#include <cuda_runtime.h>
#include <cuda_fp16.h>
#include <math.h>
#include <stdint.h>

#define NB      512
#define CHUNK   257
#define NCOEF   771
#define NFRAMES 128
#define NSAMP   32768

#define KSEG    1056            // A cols (multiple of 32, minimal padding)
#define AK      KSEG
#define BROWS   KSEG            // B rows (single fp16 segment)
#define MROWS   (NB*NFRAMES)    // 65536
#define NCHUNK  33              // 1056 / 32
#define NSEGQ   8
#define FSEG    (NFRAMES/NSEGQ)
#define NSPLIT  8
#define ISEG    64
#define NBASIS  33              // basis CTAs (1056 / 32 rows)
// Per-row fp16 layout (1056 cols): [0,514) current, [514,520) zero,
// [520,1034) shifted (16B-aligned), [1034,1056) zero.

__device__ __half    g_A[(size_t)MROWS * AK];    // ~138.4 MB
__device__ __half    g_B[(size_t)BROWS * 256];   // ~0.54 MB
__device__ float     g_part[NSPLIT * NB * CHUNK * 3];
__device__ float4    g_par[NB * CHUNK];
__device__ float     g_ss[NB];
__device__ unsigned  g_cnt[NB];
__device__ unsigned  g_pcnt[NB / 8];

// ---------------------------------------------------------------------------
// kP1a: split-K selection GEMM partials + fused combine/activations.
// grid (64, NSPLIT+1). blockIdx.y == NSPLIT builds the DFT basis.
// The 8th split CTA per batch-group (finisher) combines partials in fixed
// sp order, applies activations, writes g_par, resets g_ss/g_cnt/g_pcnt.
// ---------------------------------------------------------------------------
#define BPB 8
__global__ void __launch_bounds__(288) kP1a(const float* __restrict__ sel,
                                            const float* __restrict__ items) {
    const int tid = threadIdx.x;

    if (blockIdx.y == NSPLIT) {
        // ---- basis blocks: B[1056][256], Hann folded, fp16 ----
        __shared__ float2 tw[512];
        if (blockIdx.x >= NBASIS) return;
        if (tid < 256) {
            float sn, cs;
            sincosf((float)tid * (6.283185307179586f / 512.f), &sn, &cs);
            tw[tid] = make_float2(cs, sn);
            sincosf((float)(tid + 256) * (6.283185307179586f / 512.f), &sn, &cs);
            tw[tid + 256] = make_float2(cs, sn);
        }
        __syncthreads();
        if (tid < 256) {
            const int n = tid;
            const float h1 = 0.5f - 0.5f * cosf((float)n         * (6.283185307179586f / 511.f));
            const float h2 = 0.5f - 0.5f * cosf((float)(n + 256) * (6.283185307179586f / 511.f));
#pragma unroll 1
            for (int ri = 0; ri < 32; ri++) {
                const int rr = blockIdx.x * 32 + ri;      // 0..1055
                float v = 0.f;
                if (rr < 514) {
                    const int k = rr >> 1, odd = rr & 1;
                    const float2 t = tw[(k * n) & 511];
                    v = (odd ? -t.y : t.x) * h1;
                } else if (rr >= 520 && rr < 1034) {
                    const int k = (rr - 520) >> 1, odd = (rr - 520) & 1;
                    const float2 t = tw[(k * n) & 511];
                    v = (odd ? -t.y : t.x) * h2;
                }
                g_B[(size_t)rr * 256 + n] = __float2half_rn(v);
            }
        }
        return;
    }

    // ---- split-K partial GEMM ----
    __shared__ float sh_sel[BPB * ISEG];
    __shared__ unsigned s_flag;
    const int b0  = blockIdx.x * BPB;
    const int sp  = blockIdx.y;
    const int i0  = sp * ISEG;
    const int k   = tid;

    for (int idx = tid; idx < BPB * ISEG; idx += 288) {
        const int b = idx / ISEG, ii = idx % ISEG;
        const float v = sel[(b0 + b) * 512 + i0 + ii];
        sh_sel[idx] = v > 0.f ? v : 0.f;
    }
    __syncthreads();

    if (k < CHUNK) {
        float am[BPB], ap[BPB], as_[BPB];
#pragma unroll
        for (int b = 0; b < BPB; b++) { am[b] = 0.f; ap[b] = 0.f; as_[b] = 0.f; }

        for (int ii = 0; ii < ISEG; ii++) {
            const int i = i0 + ii;
            const float i0v = items[i * NCOEF + k];
            const float i1v = items[i * NCOEF + CHUNK + k];
            const float i2v = items[i * NCOEF + 2 * CHUNK + k];
#pragma unroll
            for (int b = 0; b < BPB; b++) {
                const float s = sh_sel[b * ISEG + ii];
                am[b]  = fmaf(s, i0v, am[b]);
                ap[b]  = fmaf(s, i1v, ap[b]);
                as_[b] = fmaf(s, i2v, as_[b]);
            }
        }
#pragma unroll
        for (int b = 0; b < BPB; b++) {
            float* p = &g_part[(size_t)(((sp * NB) + b0 + b) * CHUNK + k) * 3];
            p[0] = am[b]; p[1] = ap[b]; p[2] = as_[b];
        }
    }

    // release partials, then count
    __threadfence();
    __syncthreads();
    if (tid == 0) {
        const unsigned old = atomicAdd(&g_pcnt[blockIdx.x], 1u);
        s_flag = (old == NSPLIT - 1) ? 1u : 0u;
        if (s_flag) {
            g_pcnt[blockIdx.x] = 0u;      // replay-safe reset (we own it now)
            __threadfence();              // acquire partner partials
        }
    }
    __syncthreads();

    if (s_flag) {
        // reset per-batch norm state for kG
        if (tid >= 260 && tid < 260 + BPB) g_ss[b0 + (tid - 260)] = 0.f;
        if (tid >= 270 && tid < 270 + BPB) g_cnt[b0 + (tid - 270)] = 0u;

        if (k < CHUNK) {
            const float w = (k == 0 || k == 256) ? (1.f / 512.f) : (2.f / 512.f);
#pragma unroll 1
            for (int b = 0; b < BPB; b++) {
                float am = 0.f, ap = 0.f, as_ = 0.f;
#pragma unroll
                for (int spp = 0; spp < NSPLIT; spp++) {
                    const float* p =
                        &g_part[(size_t)(((spp * NB) + b0 + b) * CHUNK + k) * 3];
                    am += p[0]; ap += p[1]; as_ += p[2];
                }
                const float m  = fmaf(1.f / (1.f + expf(-am)), 0.9999f * 0.5f, 0.5f);
                const float ph = tanhf(ap) * 3.14159265358979323846f;
                const float st = 1.f / (1.f + expf(-as_));
                float sn, cs;
                sincosf(ph, &sn, &cs);
                const float rRe = m * cs, rIm = m * sn;
                const float ws  = w * st;
                g_par[(b0 + b) * CHUNK + k] = make_float4(rRe, rIm, ws * rRe, ws * rIm);
            }
        }
    }
}

// ---------------------------------------------------------------------------
// kP2: segment-parallel rotator recurrence -> fp16 A, 128-bit stores.
// t<64: bins 4t..4t+3.  t==64: bin 256.  t in [65,79): pad zeroing.
// ---------------------------------------------------------------------------
__device__ __forceinline__ float2 cmul(float2 a, float2 b) {
    return make_float2(fmaf(a.x, b.x, -(a.y * b.y)), fmaf(a.x, b.y, a.y * b.x));
}
__device__ __forceinline__ float2 csq(float2 a) {
    return make_float2(fmaf(a.x, a.x, -(a.y * a.y)), 2.f * a.x * a.y);
}
__device__ __forceinline__ unsigned int pack_h2(float2 c) {
    const __half2 h = __floats2half2_rn(c.x, c.y);
    return *(const unsigned int*)&h;
}

__global__ void __launch_bounds__(96) kP2() {
    const int t = threadIdx.x;
    const int b = blockIdx.x;
    const int s = blockIdx.y;
    char* Ab = (char*)g_A;
    const size_t rowStride = (size_t)AK * 2;              // 2112 B
    const size_t base = (size_t)b * NFRAMES * rowStride;

    if (t < 64) {
        float2 r[4], c[4];
#pragma unroll
        for (int j = 0; j < 4; j++) {
            const float4 p = g_par[b * CHUNK + 4 * t + j];
            r[j] = make_float2(p.x, p.y);
            c[j] = make_float2(p.z, p.w);
        }
#pragma unroll
        for (int j = 0; j < 4; j++) {
            float2 tt = csq(csq(csq(csq(r[j]))));   // r^16
            if (s & 1) c[j] = cmul(c[j], tt);
            tt = csq(tt);
            if (s & 2) c[j] = cmul(c[j], tt);
            tt = csq(tt);
            if (s & 4) c[j] = cmul(c[j], tt);
        }
        const unsigned long long sgn = 0x8000800000000000ULL;  // odd bin in hi u32
        if (s == 0) {   // frame 0 has no previous frame
            *(ulonglong2*)(Ab + base + 1040 + 16 * t) = make_ulonglong2(0, 0);
        }
#pragma unroll 1
        for (int i = 0; i < FSEG; i++) {
            const int f = s * FSEG + i;
            const unsigned long long h01 =
                (unsigned long long)pack_h2(c[0]) | ((unsigned long long)pack_h2(c[1]) << 32);
            const unsigned long long h23 =
                (unsigned long long)pack_h2(c[2]) | ((unsigned long long)pack_h2(c[3]) << 32);

            char* rp = Ab + base + (size_t)f * rowStride;
            *(ulonglong2*)(rp + 16 * t) = make_ulonglong2(h01, h23);
            if (f + 1 < NFRAMES) {
                *(ulonglong2*)(rp + rowStride + 1040 + 16 * t) =
                    make_ulonglong2(h01 ^ sgn, h23 ^ sgn);
            }
#pragma unroll
            for (int j = 0; j < 4; j++) c[j] = cmul(c[j], r[j]);
        }
    } else if (t == 64) {
        // bin 256 (even k -> no sign flip)
        const float4 p = g_par[b * CHUNK + 256];
        const float2 r = make_float2(p.x, p.y);
        float2 c = make_float2(p.z, p.w);
        float2 tt = csq(csq(csq(csq(r))));
        if (s & 1) c = cmul(c, tt);
        tt = csq(tt);
        if (s & 2) c = cmul(c, tt);
        tt = csq(tt);
        if (s & 4) c = cmul(c, tt);
        if (s == 0) *(unsigned int*)(Ab + base + 2064) = 0u;
#pragma unroll 1
        for (int i = 0; i < FSEG; i++) {
            const int f = s * FSEG + i;
            const unsigned int hu = pack_h2(c);
            char* rp = Ab + base + (size_t)f * rowStride;
            *(unsigned int*)(rp + 1024) = hu;
            if (f + 1 < NFRAMES)
                *(unsigned int*)(rp + rowStride + 2064) = hu;
            c = cmul(c, r);
        }
    } else if (t < 79) {
        // pads: u32 idx 257..259 (cols 514..519) and 517..527 (cols 1034..1055)
        const int q = t - 65;              // 0..13
        const unsigned off = (q < 3) ? (257u + q) : (517u + (q - 3));
        unsigned int* pA32 = (unsigned int*)g_A;
#pragma unroll 1
        for (int i = 0; i < FSEG; i++) {
            const size_t rw32 = ((size_t)(b * NFRAMES + s * FSEG + i) * AK) >> 1;
            pA32[rw32 + off] = 0u;
        }
    }
}

// ---------------------------------------------------------------------------
// kG: fp16 mma.sync GEMM, BK=32, 5-stage cp.async pipeline, K = 1056.
// grid = (2, 512) (R12 proven config). Fused L2 normalization: second CTA
// of each batch rescales its own half from registers + partner from global.
// ---------------------------------------------------------------------------
#define LDA_S 40
#define LDB_S 136
#define AS_BYTES (128 * LDA_S * 2)
#define BS_BYTES (32 * LDB_S * 2)
#define NSTAGE   5
#define SMEM_KG  (NSTAGE * (AS_BYTES + BS_BYTES))

__device__ __forceinline__ void cpa16(unsigned int s, const void* g) {
    asm volatile("cp.async.cg.shared.global [%0],[%1],16;" :: "r"(s), "l"(g));
}
__device__ __forceinline__ void ldm4(unsigned int& r0, unsigned int& r1,
                                     unsigned int& r2, unsigned int& r3, unsigned int a) {
    asm volatile("ldmatrix.sync.aligned.m8n8.x4.shared.b16 {%0,%1,%2,%3},[%4];"
                 : "=r"(r0), "=r"(r1), "=r"(r2), "=r"(r3) : "r"(a));
}
__device__ __forceinline__ void ldm4t(unsigned int& r0, unsigned int& r1,
                                      unsigned int& r2, unsigned int& r3, unsigned int a) {
    asm volatile("ldmatrix.sync.aligned.m8n8.x4.trans.shared.b16 {%0,%1,%2,%3},[%4];"
                 : "=r"(r0), "=r"(r1), "=r"(r2), "=r"(r3) : "r"(a));
}
__device__ __forceinline__ void mma16816(float* c, const unsigned int* a, const unsigned int* b) {
    asm volatile("mma.sync.aligned.m16n8k16.row.col.f32.f16.f16.f32 "
                 "{%0,%1,%2,%3},{%4,%5,%6,%7},{%8,%9},{%0,%1,%2,%3};"
                 : "+f"(c[0]), "+f"(c[1]), "+f"(c[2]), "+f"(c[3])
                 : "r"(a[0]), "r"(a[1]), "r"(a[2]), "r"(a[3]), "r"(b[0]), "r"(b[1]));
}

__global__ void __launch_bounds__(256, 2) kG(float* __restrict__ out) {
    extern __shared__ __align__(16) __half dsm[];
    __shared__ float red[8];
    __shared__ unsigned s_flag;
    __shared__ float s_inv;

    const int tid   = threadIdx.x;
    const int lane  = tid & 31;
    const int wid   = tid >> 5;
    const int warpM = wid >> 2;
    const int warpN = wid & 3;
    const int mBase = blockIdx.y * 128;   // batch panel
    const int nBase = blockIdx.x * 128;   // N half

    const unsigned int base = (unsigned int)__cvta_generic_to_shared(dsm);
#define SA_STAGE(i) (base + (unsigned)(i) * AS_BYTES)
#define SB_STAGE(i) (base + (unsigned)NSTAGE * AS_BYTES + (unsigned)(i) * BS_BYTES)

    const int aRow = tid >> 2, aOff = (tid & 3) * 8;
    const int bRow = tid >> 4, bOff = (tid & 15) * 8;

    const __half* A = g_A;
    const __half* B = g_B;

    float c[4][4][4];
#pragma unroll
    for (int i = 0; i < 4; i++)
#pragma unroll
        for (int j = 0; j < 4; j++)
#pragma unroll
            for (int q = 0; q < 4; q++) c[i][j][q] = 0.f;

    const int lrow  = (lane & 7) + ((lane >> 3) & 1) * 8;
    const int lcol8 = (lane >> 4) * 8;

#define PREFETCH(cIdx, st)                                                            \
    {                                                                                 \
        const int c_ = (cIdx);                                                        \
        const int aCol = c_ * 32;                                                     \
        const int bR   = c_ * 32;                                                     \
        const unsigned int sa = SA_STAGE(st);                                         \
        const unsigned int sb = SB_STAGE(st);                                         \
        cpa16(sa + (unsigned)(aRow * LDA_S + aOff) * 2,                               \
              A + (size_t)(mBase + aRow) * AK + aCol + aOff);                         \
        cpa16(sa + (unsigned)((aRow + 64) * LDA_S + aOff) * 2,                        \
              A + (size_t)(mBase + aRow + 64) * AK + aCol + aOff);                    \
        cpa16(sb + (unsigned)(bRow * LDB_S + bOff) * 2,                               \
              B + (size_t)(bR + bRow) * 256 + nBase + bOff);                          \
        cpa16(sb + (unsigned)((bRow + 16) * LDB_S + bOff) * 2,                        \
              B + (size_t)(bR + bRow + 16) * 256 + nBase + bOff);                     \
        asm volatile("cp.async.commit_group;");                                       \
    }

    PREFETCH(0, 0)
    PREFETCH(1, 1)
    PREFETCH(2, 2)
    PREFETCH(3, 3)

    int stg = 0;
    for (int ch = 0; ch < NCHUNK; ch++) {
        if (ch + 4 < NCHUNK) {
            asm volatile("cp.async.wait_group 3;");
        } else {
            asm volatile("cp.async.wait_group 0;");
        }
        __syncthreads();
        if (ch + 4 < NCHUNK) {
            int pstg = stg + 4; if (pstg >= NSTAGE) pstg -= NSTAGE;
            PREFETCH(ch + 4, pstg)
        }

        const unsigned int sAcur = SA_STAGE(stg);
        const unsigned int sBcur = SB_STAGE(stg);
#pragma unroll
        for (int kk = 0; kk < 32; kk += 16) {
            unsigned int af[4][4];
#pragma unroll
            for (int mi = 0; mi < 4; mi++) {
                const unsigned int addr = sAcur +
                    (unsigned)((warpM * 64 + mi * 16 + lrow) * LDA_S + kk + lcol8) * 2;
                ldm4(af[mi][0], af[mi][1], af[mi][2], af[mi][3], addr);
            }
            unsigned int bf[4][2];
#pragma unroll
            for (int nj = 0; nj < 2; nj++) {
                const unsigned int addr = sBcur +
                    (unsigned)((kk + lrow) * LDB_S + warpN * 32 + nj * 16 + lcol8) * 2;
                unsigned int r0, r1, r2, r3;
                ldm4t(r0, r1, r2, r3, addr);
                bf[nj * 2][0] = r0; bf[nj * 2][1] = r1;
                bf[nj * 2 + 1][0] = r2; bf[nj * 2 + 1][1] = r3;
            }
#pragma unroll
            for (int mi = 0; mi < 4; mi++)
#pragma unroll
                for (int nf = 0; nf < 4; nf++)
                    mma16816(c[mi][nf], af[mi], bf[nf]);
        }
        if (++stg == NSTAGE) stg = 0;
    }

    // ---- store unnormalized + partial sum of squares ----
    float ss = 0.f;
#pragma unroll
    for (int mi = 0; mi < 4; mi++) {
#pragma unroll
        for (int nf = 0; nf < 4; nf++) {
            const int r = mBase + warpM * 64 + mi * 16 + (lane >> 2);
            const int n = nBase + warpN * 32 + nf * 8 + (lane & 3) * 2;
            float2* p0 = (float2*)(out + (size_t)r * 256 + n);
            float2* p1 = (float2*)(out + (size_t)(r + 8) * 256 + n);
            *p0 = make_float2(c[mi][nf][0], c[mi][nf][1]);
            *p1 = make_float2(c[mi][nf][2], c[mi][nf][3]);
#pragma unroll
            for (int q = 0; q < 4; q++) ss = fmaf(c[mi][nf][q], c[mi][nf][q], ss);
        }
    }
#pragma unroll
    for (int o = 16; o > 0; o >>= 1) ss += __shfl_xor_sync(0xffffffffu, ss, o);
    if (lane == 0) red[wid] = ss;

    // release: make this CTA's stores visible before signaling
    __threadfence();
    __syncthreads();

    if (tid == 0) {
        float tot = 0.f;
#pragma unroll
        for (int i = 0; i < 8; i++) tot += red[i];
        atomicAdd(&g_ss[blockIdx.y], tot);
        __threadfence();                                  // order ss-add before cnt-add
        const unsigned old = atomicAdd(&g_cnt[blockIdx.y], 1u);
        s_flag = old;                                     // 1 -> we are the finisher
        if (old == 1u) {
            __threadfence();                              // acquire
            s_inv = 1.f / (sqrtf(g_ss[blockIdx.y]) + 1e-8f);
        }
    }
    __syncthreads();

    if (s_flag == 1u) {
        const float inv = s_inv;
        // own half: rescale from still-live registers (no global re-read)
#pragma unroll
        for (int mi = 0; mi < 4; mi++) {
#pragma unroll
            for (int nf = 0; nf < 4; nf++) {
                const int r = mBase + warpM * 64 + mi * 16 + (lane >> 2);
                const int n = nBase + warpN * 32 + nf * 8 + (lane & 3) * 2;
                float2* p0 = (float2*)(out + (size_t)r * 256 + n);
                float2* p1 = (float2*)(out + (size_t)(r + 8) * 256 + n);
                *p0 = make_float2(c[mi][nf][0] * inv, c[mi][nf][1] * inv);
                *p1 = make_float2(c[mi][nf][2] * inv, c[mi][nf][3] * inv);
            }
        }
        // partner half: read-scale-write (L2-hot)
        const int pbase = nBase ^ 128;
#pragma unroll 4
        for (int i = tid; i < 128 * 32; i += 256) {
            const int row = i >> 5, c4 = i & 31;
            float4* p = (float4*)(out + (size_t)(mBase + row) * 256 + pbase) + c4;
            float4 v = *p;
            v.x *= inv; v.y *= inv; v.z *= inv; v.w *= inv;
            *p = v;
        }
    }
#undef PREFETCH
#undef SA_STAGE
#undef SB_STAGE
}

extern "C" void kernel_launch(void* const* d_in, const int* in_sizes, int n_in,
                              void* d_out, int out_size) {
    const float* sel   = (const float*)d_in[0];
    const float* items = (const float*)d_in[1];
    if (n_in >= 2 && in_sizes[0] == 512 * 771) {
        items = (const float*)d_in[0];
        sel   = (const float*)d_in[1];
    }
    float* out = (float*)d_out;

    static bool attr_set = false;
    if (!attr_set) {
        cudaFuncSetAttribute(kG, cudaFuncAttributeMaxDynamicSharedMemorySize, SMEM_KG);
        attr_set = true;
    }

    kP1a<<<dim3(NB / BPB, NSPLIT + 1), 288>>>(sel, items);
    kP2<<<dim3(NB, NSEGQ), 96>>>();
    kG<<<dim3(2, MROWS / 128), 256, SMEM_KG>>>(out);
}

// round 15
// speedup vs baseline: 1.0596x; 1.0082x over previous
#include <cuda_runtime.h>
#include <cuda_fp16.h>
#include <math.h>
#include <stdint.h>

#define NB      512
#define CHUNK   257
#define NCOEF   771
#define NFRAMES 128
#define NSAMP   32768

#define AKC     544             // compact A cols (17 * 32)
#define ROWSB   129             // rows per batch (zero row + 128 frames)
#define BROWS   1088            // B rows: [cur 544 | shifted 544]
#define NCHUNK  34              // 1088 / 32
#define NSEGQ   8
#define FSEG    (NFRAMES/NSEGQ)
#define NSPLIT  16
#define ISEG    32
#define NBASIS  34              // basis CTAs (1088 / 32 rows)
// Compact A row layout (544 fp16): [0,514) spectrum (2k=Re,2k+1=Im),
// [514,544) zero pad. Row 0 of each batch = zeros (f = -1 boundary).

__device__ __half    g_A[(size_t)NB * ROWSB * AKC];   // ~71.9 MB
__device__ __half    g_B[(size_t)BROWS * 256];        // ~0.56 MB
__device__ float     g_part[NSPLIT * NB * CHUNK * 3];
__device__ float4    g_par[NB * CHUNK];
__device__ float     g_ss[NB];
__device__ unsigned  g_cnt[NB];
__device__ unsigned  g_pcnt[NB / 8];

// ---------------------------------------------------------------------------
// kP1a: split-K selection GEMM partials + fused combine/activations.
// grid (64, NSPLIT+1). blockIdx.y == NSPLIT builds the DFT basis.
// ---------------------------------------------------------------------------
#define BPB 8
__global__ void __launch_bounds__(288) kP1a(const float* __restrict__ sel,
                                            const float* __restrict__ items) {
    const int tid = threadIdx.x;

    if (blockIdx.y == NSPLIT) {
        // ---- basis: B[1088][256]. Rows 0..543: hann1*trig (current frame).
        // Rows 544..1087: hann2*trig*(-1)^k (shifted frame, sign folded). ----
        __shared__ float2 tw[512];
        if (blockIdx.x >= NBASIS) return;
        if (tid < 256) {
            float sn, cs;
            sincosf((float)tid * (6.283185307179586f / 512.f), &sn, &cs);
            tw[tid] = make_float2(cs, sn);
            sincosf((float)(tid + 256) * (6.283185307179586f / 512.f), &sn, &cs);
            tw[tid + 256] = make_float2(cs, sn);
        }
        __syncthreads();
        if (tid < 256) {
            const int n = tid;
            const float h1 = 0.5f - 0.5f * cosf((float)n         * (6.283185307179586f / 511.f));
            const float h2 = 0.5f - 0.5f * cosf((float)(n + 256) * (6.283185307179586f / 511.f));
#pragma unroll 1
            for (int ri = 0; ri < 32; ri++) {
                const int row = blockIdx.x * 32 + ri;     // 0..1087
                const int region = row / AKC;             // 0=current, 1=shifted
                const int rr = row - region * AKC;
                float v = 0.f;
                if (rr < 514) {
                    const int k = rr >> 1, odd = rr & 1;
                    const float2 t = tw[(k * n) & 511];
                    const float trig = odd ? -t.y : t.x;
                    if (region == 0) v = trig * h1;
                    else             v = trig * h2 * ((k & 1) ? -1.f : 1.f);
                }
                g_B[(size_t)row * 256 + n] = __float2half_rn(v);
            }
        }
        return;
    }

    // ---- split-K partial GEMM ----
    __shared__ float sh_sel[BPB * ISEG];
    __shared__ unsigned s_flag;
    const int b0  = blockIdx.x * BPB;
    const int sp  = blockIdx.y;
    const int i0  = sp * ISEG;
    const int k   = tid;

    for (int idx = tid; idx < BPB * ISEG; idx += 288) {
        const int b = idx / ISEG, ii = idx % ISEG;
        const float v = sel[(b0 + b) * 512 + i0 + ii];
        sh_sel[idx] = v > 0.f ? v : 0.f;
    }
    __syncthreads();

    if (k < CHUNK) {
        float am[BPB], ap[BPB], as_[BPB];
#pragma unroll
        for (int b = 0; b < BPB; b++) { am[b] = 0.f; ap[b] = 0.f; as_[b] = 0.f; }

        for (int ii = 0; ii < ISEG; ii++) {
            const int i = i0 + ii;
            const float i0v = items[i * NCOEF + k];
            const float i1v = items[i * NCOEF + CHUNK + k];
            const float i2v = items[i * NCOEF + 2 * CHUNK + k];
#pragma unroll
            for (int b = 0; b < BPB; b++) {
                const float s = sh_sel[b * ISEG + ii];
                am[b]  = fmaf(s, i0v, am[b]);
                ap[b]  = fmaf(s, i1v, ap[b]);
                as_[b] = fmaf(s, i2v, as_[b]);
            }
        }
#pragma unroll
        for (int b = 0; b < BPB; b++) {
            float* p = &g_part[(size_t)(((sp * NB) + b0 + b) * CHUNK + k) * 3];
            p[0] = am[b]; p[1] = ap[b]; p[2] = as_[b];
        }
    }

    // release partials, then count
    __threadfence();
    __syncthreads();
    if (tid == 0) {
        const unsigned old = atomicAdd(&g_pcnt[blockIdx.x], 1u);
        s_flag = (old == NSPLIT - 1) ? 1u : 0u;
        if (s_flag) {
            g_pcnt[blockIdx.x] = 0u;      // replay-safe reset (we own it now)
            __threadfence();              // acquire partner partials
        }
    }
    __syncthreads();

    if (s_flag) {
        // reset per-batch norm state for kG
        if (tid >= 260 && tid < 260 + BPB) g_ss[b0 + (tid - 260)] = 0.f;
        if (tid >= 270 && tid < 270 + BPB) g_cnt[b0 + (tid - 270)] = 0u;

        if (k < CHUNK) {
            const float w = (k == 0 || k == 256) ? (1.f / 512.f) : (2.f / 512.f);
#pragma unroll 1
            for (int b = 0; b < BPB; b++) {
                float am = 0.f, ap = 0.f, as_ = 0.f;
#pragma unroll
                for (int spp = 0; spp < NSPLIT; spp++) {
                    const float* p =
                        &g_part[(size_t)(((spp * NB) + b0 + b) * CHUNK + k) * 3];
                    am += p[0]; ap += p[1]; as_ += p[2];
                }
                const float m  = fmaf(1.f / (1.f + expf(-am)), 0.9999f * 0.5f, 0.5f);
                const float ph = tanhf(ap) * 3.14159265358979323846f;
                const float st = 1.f / (1.f + expf(-as_));
                float sn, cs;
                sincosf(ph, &sn, &cs);
                const float rRe = m * cs, rIm = m * sn;
                const float ws  = w * st;
                g_par[(b0 + b) * CHUNK + k] = make_float4(rRe, rIm, ws * rRe, ws * rIm);
            }
        }
    }
}

// ---------------------------------------------------------------------------
// kP2: segment-parallel rotator recurrence -> compact fp16 A (single write
// per frame, no shifted duplication). t<64: bins 4t..4t+3. t==64: bin 256.
// t in [65,80): pad zeroing. s==0 additionally zeroes the f=-1 boundary row.
// ---------------------------------------------------------------------------
__device__ __forceinline__ float2 cmul(float2 a, float2 b) {
    return make_float2(fmaf(a.x, b.x, -(a.y * b.y)), fmaf(a.x, b.y, a.y * b.x));
}
__device__ __forceinline__ float2 csq(float2 a) {
    return make_float2(fmaf(a.x, a.x, -(a.y * a.y)), 2.f * a.x * a.y);
}
__device__ __forceinline__ unsigned int pack_h2(float2 c) {
    const __half2 h = __floats2half2_rn(c.x, c.y);
    return *(const unsigned int*)&h;
}

__global__ void __launch_bounds__(96) kP2() {
    const int t = threadIdx.x;
    const int b = blockIdx.x;
    const int s = blockIdx.y;
    char* Ab = (char*)g_A;
    const size_t rowStride = (size_t)AKC * 2;             // 1088 B
    const size_t base = (size_t)b * ROWSB * rowStride;

    if (s == 0 && t < 68)   // zero the f = -1 boundary row (1088 B)
        *(ulonglong2*)(Ab + base + 16 * t) = make_ulonglong2(0, 0);

    if (t < 64) {
        float2 r[4], c[4];
#pragma unroll
        for (int j = 0; j < 4; j++) {
            const float4 p = g_par[b * CHUNK + 4 * t + j];
            r[j] = make_float2(p.x, p.y);
            c[j] = make_float2(p.z, p.w);
        }
#pragma unroll
        for (int j = 0; j < 4; j++) {
            float2 tt = csq(csq(csq(csq(r[j]))));   // r^16
            if (s & 1) c[j] = cmul(c[j], tt);
            tt = csq(tt);
            if (s & 2) c[j] = cmul(c[j], tt);
            tt = csq(tt);
            if (s & 4) c[j] = cmul(c[j], tt);
        }
#pragma unroll 1
        for (int i = 0; i < FSEG; i++) {
            const int f = s * FSEG + i;
            const unsigned long long h01 =
                (unsigned long long)pack_h2(c[0]) | ((unsigned long long)pack_h2(c[1]) << 32);
            const unsigned long long h23 =
                (unsigned long long)pack_h2(c[2]) | ((unsigned long long)pack_h2(c[3]) << 32);
            *(ulonglong2*)(Ab + base + (size_t)(1 + f) * rowStride + 16 * t) =
                make_ulonglong2(h01, h23);
#pragma unroll
            for (int j = 0; j < 4; j++) c[j] = cmul(c[j], r[j]);
        }
    } else if (t == 64) {
        // bin 256
        const float4 p = g_par[b * CHUNK + 256];
        const float2 r = make_float2(p.x, p.y);
        float2 c = make_float2(p.z, p.w);
        float2 tt = csq(csq(csq(csq(r))));
        if (s & 1) c = cmul(c, tt);
        tt = csq(tt);
        if (s & 2) c = cmul(c, tt);
        tt = csq(tt);
        if (s & 4) c = cmul(c, tt);
#pragma unroll 1
        for (int i = 0; i < FSEG; i++) {
            const int f = s * FSEG + i;
            *(unsigned int*)(Ab + base + (size_t)(1 + f) * rowStride + 1024) = pack_h2(c);
            c = cmul(c, r);
        }
    } else if (t < 80) {
        // pads: cols 514..543 = 15 u32 per row (byte 1028..1087)
        const int q = t - 65;              // 0..14
#pragma unroll 1
        for (int i = 0; i < FSEG; i++) {
            *(unsigned int*)(Ab + base + (size_t)(1 + s * FSEG + i) * rowStride +
                             1028 + 4 * q) = 0u;
        }
    }
}

// ---------------------------------------------------------------------------
// kG: fp16 mma.sync GEMM, BK=32, 5-stage cp.async pipeline, K = 1088.
// Chunks 0..16 read compact-A rows (f), chunks 17..33 read rows (f-1);
// the (-1)^k sign lives in B rows 544..1087. grid = (2, 512).
// Fused L2 normalization via release/acquire finisher (proven protocol).
// ---------------------------------------------------------------------------
#define LDA_S 40
#define LDB_S 136
#define AS_BYTES (128 * LDA_S * 2)
#define BS_BYTES (32 * LDB_S * 2)
#define NSTAGE   5
#define SMEM_KG  (NSTAGE * (AS_BYTES + BS_BYTES))

__device__ __forceinline__ void cpa16(unsigned int s, const void* g) {
    asm volatile("cp.async.cg.shared.global [%0],[%1],16;" :: "r"(s), "l"(g));
}
__device__ __forceinline__ void ldm4(unsigned int& r0, unsigned int& r1,
                                     unsigned int& r2, unsigned int& r3, unsigned int a) {
    asm volatile("ldmatrix.sync.aligned.m8n8.x4.shared.b16 {%0,%1,%2,%3},[%4];"
                 : "=r"(r0), "=r"(r1), "=r"(r2), "=r"(r3) : "r"(a));
}
__device__ __forceinline__ void ldm4t(unsigned int& r0, unsigned int& r1,
                                      unsigned int& r2, unsigned int& r3, unsigned int a) {
    asm volatile("ldmatrix.sync.aligned.m8n8.x4.trans.shared.b16 {%0,%1,%2,%3},[%4];"
                 : "=r"(r0), "=r"(r1), "=r"(r2), "=r"(r3) : "r"(a));
}
__device__ __forceinline__ void mma16816(float* c, const unsigned int* a, const unsigned int* b) {
    asm volatile("mma.sync.aligned.m16n8k16.row.col.f32.f16.f16.f32 "
                 "{%0,%1,%2,%3},{%4,%5,%6,%7},{%8,%9},{%0,%1,%2,%3};"
                 : "+f"(c[0]), "+f"(c[1]), "+f"(c[2]), "+f"(c[3])
                 : "r"(a[0]), "r"(a[1]), "r"(a[2]), "r"(a[3]), "r"(b[0]), "r"(b[1]));
}

__global__ void __launch_bounds__(256, 2) kG(float* __restrict__ out) {
    extern __shared__ __align__(16) __half dsm[];
    __shared__ float red[8];
    __shared__ unsigned s_flag;
    __shared__ float s_inv;

    const int tid   = threadIdx.x;
    const int lane  = tid & 31;
    const int wid   = tid >> 5;
    const int warpM = wid >> 2;
    const int warpN = wid & 3;
    const int mBase = blockIdx.y * 128;                   // output row panel
    const int nBase = blockIdx.x * 128;                   // N half
    const size_t aBase = (size_t)blockIdx.y * ROWSB * AKC;  // compact-A batch base

    const unsigned int base = (unsigned int)__cvta_generic_to_shared(dsm);
#define SA_STAGE(i) (base + (unsigned)(i) * AS_BYTES)
#define SB_STAGE(i) (base + (unsigned)NSTAGE * AS_BYTES + (unsigned)(i) * BS_BYTES)

    const int aRow = tid >> 2, aOff = (tid & 3) * 8;
    const int bRow = tid >> 4, bOff = (tid & 15) * 8;

    const __half* A = g_A;
    const __half* B = g_B;

    float c[4][4][4];
#pragma unroll
    for (int i = 0; i < 4; i++)
#pragma unroll
        for (int j = 0; j < 4; j++)
#pragma unroll
            for (int q = 0; q < 4; q++) c[i][j][q] = 0.f;

    const int lrow  = (lane & 7) + ((lane >> 3) & 1) * 8;
    const int lcol8 = (lane >> 4) * 8;

#define PREFETCH(cIdx, st)                                                            \
    {                                                                                 \
        const int c_ = (cIdx);                                                        \
        const int cc = (c_ < 17) ? c_ : (c_ - 17);                                    \
        const int ro = (c_ < 17) ? 1 : 0;   /* current: row f+1; shifted: row f */    \
        const int bR = c_ * 32;                                                       \
        const unsigned int sa = SA_STAGE(st);                                         \
        const unsigned int sb = SB_STAGE(st);                                         \
        const __half* ap = A + aBase + (size_t)(aRow + ro) * AKC + cc * 32 + aOff;    \
        cpa16(sa + (unsigned)(aRow * LDA_S + aOff) * 2, ap);                          \
        cpa16(sa + (unsigned)((aRow + 64) * LDA_S + aOff) * 2, ap + 64 * AKC);        \
        cpa16(sb + (unsigned)(bRow * LDB_S + bOff) * 2,                               \
              B + (size_t)(bR + bRow) * 256 + nBase + bOff);                          \
        cpa16(sb + (unsigned)((bRow + 16) * LDB_S + bOff) * 2,                        \
              B + (size_t)(bR + bRow + 16) * 256 + nBase + bOff);                     \
        asm volatile("cp.async.commit_group;");                                       \
    }

    PREFETCH(0, 0)
    PREFETCH(1, 1)
    PREFETCH(2, 2)
    PREFETCH(3, 3)

    int stg = 0;
    for (int ch = 0; ch < NCHUNK; ch++) {
        if (ch + 4 < NCHUNK) {
            asm volatile("cp.async.wait_group 3;");
        } else {
            asm volatile("cp.async.wait_group 0;");
        }
        __syncthreads();
        if (ch + 4 < NCHUNK) {
            int pstg = stg + 4; if (pstg >= NSTAGE) pstg -= NSTAGE;
            PREFETCH(ch + 4, pstg)
        }

        const unsigned int sAcur = SA_STAGE(stg);
        const unsigned int sBcur = SB_STAGE(stg);
#pragma unroll
        for (int kk = 0; kk < 32; kk += 16) {
            unsigned int af[4][4];
#pragma unroll
            for (int mi = 0; mi < 4; mi++) {
                const unsigned int addr = sAcur +
                    (unsigned)((warpM * 64 + mi * 16 + lrow) * LDA_S + kk + lcol8) * 2;
                ldm4(af[mi][0], af[mi][1], af[mi][2], af[mi][3], addr);
            }
            unsigned int bf[4][2];
#pragma unroll
            for (int nj = 0; nj < 2; nj++) {
                const unsigned int addr = sBcur +
                    (unsigned)((kk + lrow) * LDB_S + warpN * 32 + nj * 16 + lcol8) * 2;
                unsigned int r0, r1, r2, r3;
                ldm4t(r0, r1, r2, r3, addr);
                bf[nj * 2][0] = r0; bf[nj * 2][1] = r1;
                bf[nj * 2 + 1][0] = r2; bf[nj * 2 + 1][1] = r3;
            }
#pragma unroll
            for (int mi = 0; mi < 4; mi++)
#pragma unroll
                for (int nf = 0; nf < 4; nf++)
                    mma16816(c[mi][nf], af[mi], bf[nf]);
        }
        if (++stg == NSTAGE) stg = 0;
    }

    // ---- store unnormalized + partial sum of squares ----
    float ss = 0.f;
#pragma unroll
    for (int mi = 0; mi < 4; mi++) {
#pragma unroll
        for (int nf = 0; nf < 4; nf++) {
            const int r = mBase + warpM * 64 + mi * 16 + (lane >> 2);
            const int n = nBase + warpN * 32 + nf * 8 + (lane & 3) * 2;
            float2* p0 = (float2*)(out + (size_t)r * 256 + n);
            float2* p1 = (float2*)(out + (size_t)(r + 8) * 256 + n);
            *p0 = make_float2(c[mi][nf][0], c[mi][nf][1]);
            *p1 = make_float2(c[mi][nf][2], c[mi][nf][3]);
#pragma unroll
            for (int q = 0; q < 4; q++) ss = fmaf(c[mi][nf][q], c[mi][nf][q], ss);
        }
    }
#pragma unroll
    for (int o = 16; o > 0; o >>= 1) ss += __shfl_xor_sync(0xffffffffu, ss, o);
    if (lane == 0) red[wid] = ss;

    // release: make this CTA's stores visible before signaling
    __threadfence();
    __syncthreads();

    if (tid == 0) {
        float tot = 0.f;
#pragma unroll
        for (int i = 0; i < 8; i++) tot += red[i];
        atomicAdd(&g_ss[blockIdx.y], tot);
        __threadfence();                                  // order ss-add before cnt-add
        const unsigned old = atomicAdd(&g_cnt[blockIdx.y], 1u);
        s_flag = old;                                     // 1 -> we are the finisher
        if (old == 1u) {
            __threadfence();                              // acquire
            s_inv = 1.f / (sqrtf(g_ss[blockIdx.y]) + 1e-8f);
        }
    }
    __syncthreads();

    if (s_flag == 1u) {
        const float inv = s_inv;
        // own half: rescale from still-live registers (no global re-read)
#pragma unroll
        for (int mi = 0; mi < 4; mi++) {
#pragma unroll
            for (int nf = 0; nf < 4; nf++) {
                const int r = mBase + warpM * 64 + mi * 16 + (lane >> 2);
                const int n = nBase + warpN * 32 + nf * 8 + (lane & 3) * 2;
                float2* p0 = (float2*)(out + (size_t)r * 256 + n);
                float2* p1 = (float2*)(out + (size_t)(r + 8) * 256 + n);
                *p0 = make_float2(c[mi][nf][0] * inv, c[mi][nf][1] * inv);
                *p1 = make_float2(c[mi][nf][2] * inv, c[mi][nf][3] * inv);
            }
        }
        // partner half: read-scale-write (L2-hot)
        const int pbase = nBase ^ 128;
#pragma unroll 4
        for (int i = tid; i < 128 * 32; i += 256) {
            const int row = i >> 5, c4 = i & 31;
            float4* p = (float4*)(out + (size_t)(mBase + row) * 256 + pbase) + c4;
            float4 v = *p;
            v.x *= inv; v.y *= inv; v.z *= inv; v.w *= inv;
            *p = v;
        }
    }
#undef PREFETCH
#undef SA_STAGE
#undef SB_STAGE
}

extern "C" void kernel_launch(void* const* d_in, const int* in_sizes, int n_in,
                              void* d_out, int out_size) {
    const float* sel   = (const float*)d_in[0];
    const float* items = (const float*)d_in[1];
    if (n_in >= 2 && in_sizes[0] == 512 * 771) {
        items = (const float*)d_in[0];
        sel   = (const float*)d_in[1];
    }
    float* out = (float*)d_out;

    static bool attr_set = false;
    if (!attr_set) {
        cudaFuncSetAttribute(kG, cudaFuncAttributeMaxDynamicSharedMemorySize, SMEM_KG);
        attr_set = true;
    }

    kP1a<<<dim3(NB / BPB, NSPLIT + 1), 288>>>(sel, items);
    kP2<<<dim3(NB, NSEGQ), 96>>>();
    kG<<<dim3(2, NB), 256, SMEM_KG>>>(out);
}

// round 16
// speedup vs baseline: 1.1087x; 1.0464x over previous
#include <cuda_runtime.h>
#include <cuda_fp16.h>
#include <math.h>
#include <stdint.h>

#define NB      512
#define CHUNK   257
#define NCOEF   771
#define NFRAMES 128
#define NSAMP   32768

#define AKC     544             // compact A cols (17 * 32)
#define ROWSB   129             // rows per batch (zero row + 128 frames)
#define BROWS   1088            // B rows: [cur 544 | shifted 544]
#define NCHUNK  34              // 1088 / 32
#define NSEGQ   8
#define FSEG    (NFRAMES/NSEGQ)
#define NSPLIT  8
#define ISEG    64
#define NBASIS  34              // basis CTAs (1088 / 32 rows)
// Compact A row layout (544 fp16): [0,514) spectrum (2k=Re,2k+1=Im),
// [514,544) zero pad. Row 0 of each batch = zeros (f = -1 boundary).

__device__ __half    g_A[(size_t)NB * ROWSB * AKC];   // ~71.9 MB
__device__ __half    g_B[(size_t)BROWS * 256];        // ~0.56 MB
__device__ float     g_part[NSPLIT * NB * CHUNK * 3];
__device__ float4    g_par[NB * CHUNK];
__device__ float     g_ss[NB];
__device__ unsigned  g_cnt[NB];
__device__ unsigned  g_pcnt[NB / 8];

// ---------------------------------------------------------------------------
// kP1a: split-K selection GEMM partials + fused combine/activations.
// grid (64, NSPLIT+1). blockIdx.y == NSPLIT builds the DFT basis.
// ---------------------------------------------------------------------------
#define BPB 8
__global__ void __launch_bounds__(288) kP1a(const float* __restrict__ sel,
                                            const float* __restrict__ items) {
    const int tid = threadIdx.x;

    if (blockIdx.y == NSPLIT) {
        // ---- basis: B[1088][256]. Rows 0..543: hann1*trig (current frame).
        // Rows 544..1087: hann2*trig*(-1)^k (shifted frame, sign folded). ----
        __shared__ float2 tw[512];
        if (blockIdx.x >= NBASIS) return;
        if (tid < 256) {
            float sn, cs;
            sincosf((float)tid * (6.283185307179586f / 512.f), &sn, &cs);
            tw[tid] = make_float2(cs, sn);
            sincosf((float)(tid + 256) * (6.283185307179586f / 512.f), &sn, &cs);
            tw[tid + 256] = make_float2(cs, sn);
        }
        __syncthreads();
        if (tid < 256) {
            const int n = tid;
            const float h1 = 0.5f - 0.5f * cosf((float)n         * (6.283185307179586f / 511.f));
            const float h2 = 0.5f - 0.5f * cosf((float)(n + 256) * (6.283185307179586f / 511.f));
#pragma unroll 1
            for (int ri = 0; ri < 32; ri++) {
                const int row = blockIdx.x * 32 + ri;     // 0..1087
                const int region = row / AKC;             // 0=current, 1=shifted
                const int rr = row - region * AKC;
                float v = 0.f;
                if (rr < 514) {
                    const int k = rr >> 1, odd = rr & 1;
                    const float2 t = tw[(k * n) & 511];
                    const float trig = odd ? -t.y : t.x;
                    if (region == 0) v = trig * h1;
                    else             v = trig * h2 * ((k & 1) ? -1.f : 1.f);
                }
                g_B[(size_t)row * 256 + n] = __float2half_rn(v);
            }
        }
        return;
    }

    // ---- split-K partial GEMM ----
    __shared__ float sh_sel[BPB * ISEG];
    __shared__ unsigned s_flag;
    const int b0  = blockIdx.x * BPB;
    const int sp  = blockIdx.y;
    const int i0  = sp * ISEG;
    const int k   = tid;

    for (int idx = tid; idx < BPB * ISEG; idx += 288) {
        const int b = idx / ISEG, ii = idx % ISEG;
        const float v = sel[(b0 + b) * 512 + i0 + ii];
        sh_sel[idx] = v > 0.f ? v : 0.f;
    }
    __syncthreads();

    if (k < CHUNK) {
        float am[BPB], ap[BPB], as_[BPB];
#pragma unroll
        for (int b = 0; b < BPB; b++) { am[b] = 0.f; ap[b] = 0.f; as_[b] = 0.f; }

        for (int ii = 0; ii < ISEG; ii++) {
            const int i = i0 + ii;
            const float i0v = items[i * NCOEF + k];
            const float i1v = items[i * NCOEF + CHUNK + k];
            const float i2v = items[i * NCOEF + 2 * CHUNK + k];
#pragma unroll
            for (int b = 0; b < BPB; b++) {
                const float s = sh_sel[b * ISEG + ii];
                am[b]  = fmaf(s, i0v, am[b]);
                ap[b]  = fmaf(s, i1v, ap[b]);
                as_[b] = fmaf(s, i2v, as_[b]);
            }
        }
#pragma unroll
        for (int b = 0; b < BPB; b++) {
            float* p = &g_part[(size_t)(((sp * NB) + b0 + b) * CHUNK + k) * 3];
            p[0] = am[b]; p[1] = ap[b]; p[2] = as_[b];
        }
    }

    // release partials, then count
    __threadfence();
    __syncthreads();
    if (tid == 0) {
        const unsigned old = atomicAdd(&g_pcnt[blockIdx.x], 1u);
        s_flag = (old == NSPLIT - 1) ? 1u : 0u;
        if (s_flag) {
            g_pcnt[blockIdx.x] = 0u;      // replay-safe reset (we own it now)
            __threadfence();              // acquire partner partials
        }
    }
    __syncthreads();

    if (s_flag) {
        // reset per-batch norm state for kG
        if (tid >= 260 && tid < 260 + BPB) g_ss[b0 + (tid - 260)] = 0.f;
        if (tid >= 270 && tid < 270 + BPB) g_cnt[b0 + (tid - 270)] = 0u;

        if (k < CHUNK) {
            const float w = (k == 0 || k == 256) ? (1.f / 512.f) : (2.f / 512.f);
#pragma unroll 1
            for (int b = 0; b < BPB; b++) {
                float am = 0.f, ap = 0.f, as_ = 0.f;
#pragma unroll
                for (int spp = 0; spp < NSPLIT; spp++) {
                    const float* p =
                        &g_part[(size_t)(((spp * NB) + b0 + b) * CHUNK + k) * 3];
                    am += p[0]; ap += p[1]; as_ += p[2];
                }
                const float m  = fmaf(1.f / (1.f + expf(-am)), 0.9999f * 0.5f, 0.5f);
                const float ph = tanhf(ap) * 3.14159265358979323846f;
                const float st = 1.f / (1.f + expf(-as_));
                float sn, cs;
                sincosf(ph, &sn, &cs);
                const float rRe = m * cs, rIm = m * sn;
                const float ws  = w * st;
                g_par[(b0 + b) * CHUNK + k] = make_float4(rRe, rIm, ws * rRe, ws * rIm);
            }
        }
    }
}

// ---------------------------------------------------------------------------
// kP2: segment-parallel rotator recurrence -> compact fp16 A (single write
// per frame, no shifted duplication). t<64: bins 4t..4t+3. t==64: bin 256.
// t in [65,80): pad zeroing. s==0 additionally zeroes the f=-1 boundary row.
// ---------------------------------------------------------------------------
__device__ __forceinline__ float2 cmul(float2 a, float2 b) {
    return make_float2(fmaf(a.x, b.x, -(a.y * b.y)), fmaf(a.x, b.y, a.y * b.x));
}
__device__ __forceinline__ float2 csq(float2 a) {
    return make_float2(fmaf(a.x, a.x, -(a.y * a.y)), 2.f * a.x * a.y);
}
__device__ __forceinline__ unsigned int pack_h2(float2 c) {
    const __half2 h = __floats2half2_rn(c.x, c.y);
    return *(const unsigned int*)&h;
}

__global__ void __launch_bounds__(96) kP2() {
    const int t = threadIdx.x;
    const int b = blockIdx.x;
    const int s = blockIdx.y;
    char* Ab = (char*)g_A;
    const size_t rowStride = (size_t)AKC * 2;             // 1088 B
    const size_t base = (size_t)b * ROWSB * rowStride;

    if (s == 0 && t < 68)   // zero the f = -1 boundary row (1088 B)
        *(ulonglong2*)(Ab + base + 16 * t) = make_ulonglong2(0, 0);

    if (t < 64) {
        float2 r[4], c[4];
#pragma unroll
        for (int j = 0; j < 4; j++) {
            const float4 p = g_par[b * CHUNK + 4 * t + j];
            r[j] = make_float2(p.x, p.y);
            c[j] = make_float2(p.z, p.w);
        }
#pragma unroll
        for (int j = 0; j < 4; j++) {
            float2 tt = csq(csq(csq(csq(r[j]))));   // r^16
            if (s & 1) c[j] = cmul(c[j], tt);
            tt = csq(tt);
            if (s & 2) c[j] = cmul(c[j], tt);
            tt = csq(tt);
            if (s & 4) c[j] = cmul(c[j], tt);
        }
#pragma unroll 1
        for (int i = 0; i < FSEG; i++) {
            const int f = s * FSEG + i;
            const unsigned long long h01 =
                (unsigned long long)pack_h2(c[0]) | ((unsigned long long)pack_h2(c[1]) << 32);
            const unsigned long long h23 =
                (unsigned long long)pack_h2(c[2]) | ((unsigned long long)pack_h2(c[3]) << 32);
            *(ulonglong2*)(Ab + base + (size_t)(1 + f) * rowStride + 16 * t) =
                make_ulonglong2(h01, h23);
#pragma unroll
            for (int j = 0; j < 4; j++) c[j] = cmul(c[j], r[j]);
        }
    } else if (t == 64) {
        // bin 256
        const float4 p = g_par[b * CHUNK + 256];
        const float2 r = make_float2(p.x, p.y);
        float2 c = make_float2(p.z, p.w);
        float2 tt = csq(csq(csq(csq(r))));
        if (s & 1) c = cmul(c, tt);
        tt = csq(tt);
        if (s & 2) c = cmul(c, tt);
        tt = csq(tt);
        if (s & 4) c = cmul(c, tt);
#pragma unroll 1
        for (int i = 0; i < FSEG; i++) {
            const int f = s * FSEG + i;
            *(unsigned int*)(Ab + base + (size_t)(1 + f) * rowStride + 1024) = pack_h2(c);
            c = cmul(c, r);
        }
    } else if (t < 80) {
        // pads: cols 514..543 = 15 u32 per row (byte 1028..1087)
        const int q = t - 65;              // 0..14
#pragma unroll 1
        for (int i = 0; i < FSEG; i++) {
            *(unsigned int*)(Ab + base + (size_t)(1 + s * FSEG + i) * rowStride +
                             1028 + 4 * q) = 0u;
        }
    }
}

// ---------------------------------------------------------------------------
// kG: fp16 mma.sync GEMM, BK=32, 5-stage cp.async pipeline, K = 1088.
// Chunks 0..16 read compact-A rows (f), chunks 17..33 read rows (f-1);
// the (-1)^k sign lives in B rows 544..1087. grid = (2, 512).
// Fused L2 normalization via release/acquire finisher (proven protocol).
// ---------------------------------------------------------------------------
#define LDA_S 40
#define LDB_S 136
#define AS_BYTES (128 * LDA_S * 2)
#define BS_BYTES (32 * LDB_S * 2)
#define NSTAGE   5
#define SMEM_KG  (NSTAGE * (AS_BYTES + BS_BYTES))

__device__ __forceinline__ void cpa16(unsigned int s, const void* g) {
    asm volatile("cp.async.cg.shared.global [%0],[%1],16;" :: "r"(s), "l"(g));
}
__device__ __forceinline__ void ldm4(unsigned int& r0, unsigned int& r1,
                                     unsigned int& r2, unsigned int& r3, unsigned int a) {
    asm volatile("ldmatrix.sync.aligned.m8n8.x4.shared.b16 {%0,%1,%2,%3},[%4];"
                 : "=r"(r0), "=r"(r1), "=r"(r2), "=r"(r3) : "r"(a));
}
__device__ __forceinline__ void ldm4t(unsigned int& r0, unsigned int& r1,
                                      unsigned int& r2, unsigned int& r3, unsigned int a) {
    asm volatile("ldmatrix.sync.aligned.m8n8.x4.trans.shared.b16 {%0,%1,%2,%3},[%4];"
                 : "=r"(r0), "=r"(r1), "=r"(r2), "=r"(r3) : "r"(a));
}
__device__ __forceinline__ void mma16816(float* c, const unsigned int* a, const unsigned int* b) {
    asm volatile("mma.sync.aligned.m16n8k16.row.col.f32.f16.f16.f32 "
                 "{%0,%1,%2,%3},{%4,%5,%6,%7},{%8,%9},{%0,%1,%2,%3};"
                 : "+f"(c[0]), "+f"(c[1]), "+f"(c[2]), "+f"(c[3])
                 : "r"(a[0]), "r"(a[1]), "r"(a[2]), "r"(a[3]), "r"(b[0]), "r"(b[1]));
}

__global__ void __launch_bounds__(256, 2) kG(float* __restrict__ out) {
    extern __shared__ __align__(16) __half dsm[];
    __shared__ float red[8];
    __shared__ unsigned s_flag;
    __shared__ float s_inv;

    const int tid   = threadIdx.x;
    const int lane  = tid & 31;
    const int wid   = tid >> 5;
    const int warpM = wid >> 2;
    const int warpN = wid & 3;
    const int mBase = blockIdx.y * 128;                   // output row panel
    const int nBase = blockIdx.x * 128;                   // N half
    const size_t aBase = (size_t)blockIdx.y * ROWSB * AKC;  // compact-A batch base

    const unsigned int base = (unsigned int)__cvta_generic_to_shared(dsm);
#define SA_STAGE(i) (base + (unsigned)(i) * AS_BYTES)
#define SB_STAGE(i) (base + (unsigned)NSTAGE * AS_BYTES + (unsigned)(i) * BS_BYTES)

    const int aRow = tid >> 2, aOff = (tid & 3) * 8;
    const int bRow = tid >> 4, bOff = (tid & 15) * 8;

    const __half* A = g_A;
    const __half* B = g_B;

    float c[4][4][4];
#pragma unroll
    for (int i = 0; i < 4; i++)
#pragma unroll
        for (int j = 0; j < 4; j++)
#pragma unroll
            for (int q = 0; q < 4; q++) c[i][j][q] = 0.f;

    const int lrow  = (lane & 7) + ((lane >> 3) & 1) * 8;
    const int lcol8 = (lane >> 4) * 8;

#define PREFETCH(cIdx, st)                                                            \
    {                                                                                 \
        const int c_ = (cIdx);                                                        \
        const int cc = (c_ < 17) ? c_ : (c_ - 17);                                    \
        const int ro = (c_ < 17) ? 1 : 0;   /* current: row f+1; shifted: row f */    \
        const int bR = c_ * 32;                                                       \
        const unsigned int sa = SA_STAGE(st);                                         \
        const unsigned int sb = SB_STAGE(st);                                         \
        const __half* ap = A + aBase + (size_t)(aRow + ro) * AKC + cc * 32 + aOff;    \
        cpa16(sa + (unsigned)(aRow * LDA_S + aOff) * 2, ap);                          \
        cpa16(sa + (unsigned)((aRow + 64) * LDA_S + aOff) * 2, ap + 64 * AKC);        \
        cpa16(sb + (unsigned)(bRow * LDB_S + bOff) * 2,                               \
              B + (size_t)(bR + bRow) * 256 + nBase + bOff);                          \
        cpa16(sb + (unsigned)((bRow + 16) * LDB_S + bOff) * 2,                        \
              B + (size_t)(bR + bRow + 16) * 256 + nBase + bOff);                     \
        asm volatile("cp.async.commit_group;");                                       \
    }

    PREFETCH(0, 0)
    PREFETCH(1, 1)
    PREFETCH(2, 2)
    PREFETCH(3, 3)

    int stg = 0;
    for (int ch = 0; ch < NCHUNK; ch++) {
        if (ch + 4 < NCHUNK) {
            asm volatile("cp.async.wait_group 3;");
        } else {
            asm volatile("cp.async.wait_group 0;");
        }
        __syncthreads();
        if (ch + 4 < NCHUNK) {
            int pstg = stg + 4; if (pstg >= NSTAGE) pstg -= NSTAGE;
            PREFETCH(ch + 4, pstg)
        }

        const unsigned int sAcur = SA_STAGE(stg);
        const unsigned int sBcur = SB_STAGE(stg);
#pragma unroll
        for (int kk = 0; kk < 32; kk += 16) {
            unsigned int af[4][4];
#pragma unroll
            for (int mi = 0; mi < 4; mi++) {
                const unsigned int addr = sAcur +
                    (unsigned)((warpM * 64 + mi * 16 + lrow) * LDA_S + kk + lcol8) * 2;
                ldm4(af[mi][0], af[mi][1], af[mi][2], af[mi][3], addr);
            }
            unsigned int bf[4][2];
#pragma unroll
            for (int nj = 0; nj < 2; nj++) {
                const unsigned int addr = sBcur +
                    (unsigned)((kk + lrow) * LDB_S + warpN * 32 + nj * 16 + lcol8) * 2;
                unsigned int r0, r1, r2, r3;
                ldm4t(r0, r1, r2, r3, addr);
                bf[nj * 2][0] = r0; bf[nj * 2][1] = r1;
                bf[nj * 2 + 1][0] = r2; bf[nj * 2 + 1][1] = r3;
            }
#pragma unroll
            for (int mi = 0; mi < 4; mi++)
#pragma unroll
                for (int nf = 0; nf < 4; nf++)
                    mma16816(c[mi][nf], af[mi], bf[nf]);
        }
        if (++stg == NSTAGE) stg = 0;
    }

    // ---- store unnormalized + partial sum of squares ----
    float ss = 0.f;
#pragma unroll
    for (int mi = 0; mi < 4; mi++) {
#pragma unroll
        for (int nf = 0; nf < 4; nf++) {
            const int r = mBase + warpM * 64 + mi * 16 + (lane >> 2);
            const int n = nBase + warpN * 32 + nf * 8 + (lane & 3) * 2;
            float2* p0 = (float2*)(out + (size_t)r * 256 + n);
            float2* p1 = (float2*)(out + (size_t)(r + 8) * 256 + n);
            *p0 = make_float2(c[mi][nf][0], c[mi][nf][1]);
            *p1 = make_float2(c[mi][nf][2], c[mi][nf][3]);
#pragma unroll
            for (int q = 0; q < 4; q++) ss = fmaf(c[mi][nf][q], c[mi][nf][q], ss);
        }
    }
#pragma unroll
    for (int o = 16; o > 0; o >>= 1) ss += __shfl_xor_sync(0xffffffffu, ss, o);
    if (lane == 0) red[wid] = ss;

    // release: make this CTA's stores visible before signaling
    __threadfence();
    __syncthreads();

    if (tid == 0) {
        float tot = 0.f;
#pragma unroll
        for (int i = 0; i < 8; i++) tot += red[i];
        atomicAdd(&g_ss[blockIdx.y], tot);
        __threadfence();                                  // order ss-add before cnt-add
        const unsigned old = atomicAdd(&g_cnt[blockIdx.y], 1u);
        s_flag = old;                                     // 1 -> we are the finisher
        if (old == 1u) {
            __threadfence();                              // acquire
            s_inv = 1.f / (sqrtf(g_ss[blockIdx.y]) + 1e-8f);
        }
    }
    __syncthreads();

    if (s_flag == 1u) {
        const float inv = s_inv;
        // own half: rescale from still-live registers (no global re-read)
#pragma unroll
        for (int mi = 0; mi < 4; mi++) {
#pragma unroll
            for (int nf = 0; nf < 4; nf++) {
                const int r = mBase + warpM * 64 + mi * 16 + (lane >> 2);
                const int n = nBase + warpN * 32 + nf * 8 + (lane & 3) * 2;
                float2* p0 = (float2*)(out + (size_t)r * 256 + n);
                float2* p1 = (float2*)(out + (size_t)(r + 8) * 256 + n);
                *p0 = make_float2(c[mi][nf][0] * inv, c[mi][nf][1] * inv);
                *p1 = make_float2(c[mi][nf][2] * inv, c[mi][nf][3] * inv);
            }
        }
        // partner half: read-scale-write (L2-hot)
        const int pbase = nBase ^ 128;
#pragma unroll 4
        for (int i = tid; i < 128 * 32; i += 256) {
            const int row = i >> 5, c4 = i & 31;
            float4* p = (float4*)(out + (size_t)(mBase + row) * 256 + pbase) + c4;
            float4 v = *p;
            v.x *= inv; v.y *= inv; v.z *= inv; v.w *= inv;
            *p = v;
        }
    }
#undef PREFETCH
#undef SA_STAGE
#undef SB_STAGE
}

extern "C" void kernel_launch(void* const* d_in, const int* in_sizes, int n_in,
                              void* d_out, int out_size) {
    const float* sel   = (const float*)d_in[0];
    const float* items = (const float*)d_in[1];
    if (n_in >= 2 && in_sizes[0] == 512 * 771) {
        items = (const float*)d_in[0];
        sel   = (const float*)d_in[1];
    }
    float* out = (float*)d_out;

    static bool attr_set = false;
    if (!attr_set) {
        cudaFuncSetAttribute(kG, cudaFuncAttributeMaxDynamicSharedMemorySize, SMEM_KG);
        attr_set = true;
    }

    kP1a<<<dim3(NB / BPB, NSPLIT + 1), 288>>>(sel, items);
    kP2<<<dim3(NB, NSEGQ), 96>>>();
    kG<<<dim3(2, NB), 256, SMEM_KG>>>(out);
}

// round 17
// speedup vs baseline: 1.1512x; 1.0383x over previous
#include <cuda_runtime.h>
#include <cuda_fp16.h>
#include <math.h>
#include <stdint.h>

#define NB      512
#define CHUNK   257
#define NCOEF   771
#define NFRAMES 128
#define NSAMP   32768

#define AKC     544             // compact A cols (17 * 32)
#define ROWSB   129             // rows per batch (zero row + 128 frames)
#define BROWS   1088            // B rows: [cur 544 | shifted 544]
#define NCHUNK  34              // 1088 / 32
#define NSEGQ   8
#define FSEG    (NFRAMES/NSEGQ)
#define NSPLIT  8
#define ISEG    64
#define NBASIS  34              // basis CTAs (1088 / 32 rows)
// Compact A row layout (544 fp16): [0,514) spectrum (2k=Re,2k+1=Im),
// [514,544) zero pad. Row 0 of each batch = zeros (f = -1 boundary).

__device__ __half    g_A[(size_t)NB * ROWSB * AKC];   // ~71.9 MB
__device__ __half    g_B[(size_t)BROWS * 256];        // ~0.56 MB
__device__ float     g_part[NSPLIT * NB * CHUNK * 3];
__device__ float4    g_par[NB * CHUNK];
__device__ float     g_ss[NB];
__device__ unsigned  g_cnt[NB];
__device__ unsigned  g_pcnt[NB / 8];

// ---------------------------------------------------------------------------
// kP1a: split-K selection GEMM partials + fused combine/activations.
// grid (64, NSPLIT+1). blockIdx.y == NSPLIT builds the DFT basis.
// Inner loop unrolled 4x: 12 independent LDGs batched per body (MLP ~12)
// to hide L2 latency in this latency-bound kernel.
// ---------------------------------------------------------------------------
#define BPB 8
__global__ void __launch_bounds__(288) kP1a(const float* __restrict__ sel,
                                            const float* __restrict__ items) {
    const int tid = threadIdx.x;

    if (blockIdx.y == NSPLIT) {
        // ---- basis: B[1088][256]. Rows 0..543: hann1*trig (current frame).
        // Rows 544..1087: hann2*trig*(-1)^k (shifted frame, sign folded). ----
        __shared__ float2 tw[512];
        if (blockIdx.x >= NBASIS) return;
        if (tid < 256) {
            float sn, cs;
            sincosf((float)tid * (6.283185307179586f / 512.f), &sn, &cs);
            tw[tid] = make_float2(cs, sn);
            sincosf((float)(tid + 256) * (6.283185307179586f / 512.f), &sn, &cs);
            tw[tid + 256] = make_float2(cs, sn);
        }
        __syncthreads();
        if (tid < 256) {
            const int n = tid;
            const float h1 = 0.5f - 0.5f * cosf((float)n         * (6.283185307179586f / 511.f));
            const float h2 = 0.5f - 0.5f * cosf((float)(n + 256) * (6.283185307179586f / 511.f));
#pragma unroll 1
            for (int ri = 0; ri < 32; ri++) {
                const int row = blockIdx.x * 32 + ri;     // 0..1087
                const int region = row / AKC;             // 0=current, 1=shifted
                const int rr = row - region * AKC;
                float v = 0.f;
                if (rr < 514) {
                    const int k = rr >> 1, odd = rr & 1;
                    const float2 t = tw[(k * n) & 511];
                    const float trig = odd ? -t.y : t.x;
                    if (region == 0) v = trig * h1;
                    else             v = trig * h2 * ((k & 1) ? -1.f : 1.f);
                }
                g_B[(size_t)row * 256 + n] = __float2half_rn(v);
            }
        }
        return;
    }

    // ---- split-K partial GEMM ----
    __shared__ float sh_sel[BPB * ISEG];
    __shared__ unsigned s_flag;
    const int b0  = blockIdx.x * BPB;
    const int sp  = blockIdx.y;
    const int i0  = sp * ISEG;
    const int k   = tid;

    for (int idx = tid; idx < BPB * ISEG; idx += 288) {
        const int b = idx / ISEG, ii = idx % ISEG;
        const float v = sel[(b0 + b) * 512 + i0 + ii];
        sh_sel[idx] = v > 0.f ? v : 0.f;
    }
    __syncthreads();

    if (k < CHUNK) {
        float am[BPB], ap[BPB], as_[BPB];
#pragma unroll
        for (int b = 0; b < BPB; b++) { am[b] = 0.f; ap[b] = 0.f; as_[b] = 0.f; }

        const float* ibase = items + i0 * NCOEF + k;
#pragma unroll 1
        for (int ii = 0; ii < ISEG; ii += 4) {
            // batch 12 independent loads (MLP = 12)
            float v0[4], v1[4], v2[4];
#pragma unroll
            for (int u = 0; u < 4; u++) {
                const float* p = ibase + (size_t)(ii + u) * NCOEF;
                v0[u] = p[0];
                v1[u] = p[CHUNK];
                v2[u] = p[2 * CHUNK];
            }
#pragma unroll
            for (int u = 0; u < 4; u++) {
#pragma unroll
                for (int b = 0; b < BPB; b++) {
                    const float s = sh_sel[b * ISEG + ii + u];
                    am[b]  = fmaf(s, v0[u], am[b]);
                    ap[b]  = fmaf(s, v1[u], ap[b]);
                    as_[b] = fmaf(s, v2[u], as_[b]);
                }
            }
        }
#pragma unroll
        for (int b = 0; b < BPB; b++) {
            float* p = &g_part[(size_t)(((sp * NB) + b0 + b) * CHUNK + k) * 3];
            p[0] = am[b]; p[1] = ap[b]; p[2] = as_[b];
        }
    }

    // release partials, then count
    __threadfence();
    __syncthreads();
    if (tid == 0) {
        const unsigned old = atomicAdd(&g_pcnt[blockIdx.x], 1u);
        s_flag = (old == NSPLIT - 1) ? 1u : 0u;
        if (s_flag) {
            g_pcnt[blockIdx.x] = 0u;      // replay-safe reset (we own it now)
            __threadfence();              // acquire partner partials
        }
    }
    __syncthreads();

    if (s_flag) {
        // reset per-batch norm state for kG
        if (tid >= 260 && tid < 260 + BPB) g_ss[b0 + (tid - 260)] = 0.f;
        if (tid >= 270 && tid < 270 + BPB) g_cnt[b0 + (tid - 270)] = 0u;

        if (k < CHUNK) {
            const float w = (k == 0 || k == 256) ? (1.f / 512.f) : (2.f / 512.f);
#pragma unroll 1
            for (int b = 0; b < BPB; b++) {
                float am = 0.f, ap = 0.f, as_ = 0.f;
#pragma unroll
                for (int spp = 0; spp < NSPLIT; spp++) {
                    const float* p =
                        &g_part[(size_t)(((spp * NB) + b0 + b) * CHUNK + k) * 3];
                    am += p[0]; ap += p[1]; as_ += p[2];
                }
                const float m  = fmaf(1.f / (1.f + expf(-am)), 0.9999f * 0.5f, 0.5f);
                const float ph = tanhf(ap) * 3.14159265358979323846f;
                const float st = 1.f / (1.f + expf(-as_));
                float sn, cs;
                sincosf(ph, &sn, &cs);
                const float rRe = m * cs, rIm = m * sn;
                const float ws  = w * st;
                g_par[(b0 + b) * CHUNK + k] = make_float4(rRe, rIm, ws * rRe, ws * rIm);
            }
        }
    }
}

// ---------------------------------------------------------------------------
// kP2: segment-parallel rotator recurrence -> compact fp16 A (single write
// per frame, no shifted duplication). t<64: bins 4t..4t+3. t==64: bin 256.
// t in [65,80): pad zeroing. s==0 additionally zeroes the f=-1 boundary row.
// ---------------------------------------------------------------------------
__device__ __forceinline__ float2 cmul(float2 a, float2 b) {
    return make_float2(fmaf(a.x, b.x, -(a.y * b.y)), fmaf(a.x, b.y, a.y * b.x));
}
__device__ __forceinline__ float2 csq(float2 a) {
    return make_float2(fmaf(a.x, a.x, -(a.y * a.y)), 2.f * a.x * a.y);
}
__device__ __forceinline__ unsigned int pack_h2(float2 c) {
    const __half2 h = __floats2half2_rn(c.x, c.y);
    return *(const unsigned int*)&h;
}

__global__ void __launch_bounds__(96) kP2() {
    const int t = threadIdx.x;
    const int b = blockIdx.x;
    const int s = blockIdx.y;
    char* Ab = (char*)g_A;
    const size_t rowStride = (size_t)AKC * 2;             // 1088 B
    const size_t base = (size_t)b * ROWSB * rowStride;

    if (s == 0 && t < 68)   // zero the f = -1 boundary row (1088 B)
        *(ulonglong2*)(Ab + base + 16 * t) = make_ulonglong2(0, 0);

    if (t < 64) {
        float2 r[4], c[4];
#pragma unroll
        for (int j = 0; j < 4; j++) {
            const float4 p = g_par[b * CHUNK + 4 * t + j];
            r[j] = make_float2(p.x, p.y);
            c[j] = make_float2(p.z, p.w);
        }
#pragma unroll
        for (int j = 0; j < 4; j++) {
            float2 tt = csq(csq(csq(csq(r[j]))));   // r^16
            if (s & 1) c[j] = cmul(c[j], tt);
            tt = csq(tt);
            if (s & 2) c[j] = cmul(c[j], tt);
            tt = csq(tt);
            if (s & 4) c[j] = cmul(c[j], tt);
        }
#pragma unroll 1
        for (int i = 0; i < FSEG; i++) {
            const int f = s * FSEG + i;
            const unsigned long long h01 =
                (unsigned long long)pack_h2(c[0]) | ((unsigned long long)pack_h2(c[1]) << 32);
            const unsigned long long h23 =
                (unsigned long long)pack_h2(c[2]) | ((unsigned long long)pack_h2(c[3]) << 32);
            *(ulonglong2*)(Ab + base + (size_t)(1 + f) * rowStride + 16 * t) =
                make_ulonglong2(h01, h23);
#pragma unroll
            for (int j = 0; j < 4; j++) c[j] = cmul(c[j], r[j]);
        }
    } else if (t == 64) {
        // bin 256
        const float4 p = g_par[b * CHUNK + 256];
        const float2 r = make_float2(p.x, p.y);
        float2 c = make_float2(p.z, p.w);
        float2 tt = csq(csq(csq(csq(r))));
        if (s & 1) c = cmul(c, tt);
        tt = csq(tt);
        if (s & 2) c = cmul(c, tt);
        tt = csq(tt);
        if (s & 4) c = cmul(c, tt);
#pragma unroll 1
        for (int i = 0; i < FSEG; i++) {
            const int f = s * FSEG + i;
            *(unsigned int*)(Ab + base + (size_t)(1 + f) * rowStride + 1024) = pack_h2(c);
            c = cmul(c, r);
        }
    } else if (t < 80) {
        // pads: cols 514..543 = 15 u32 per row (byte 1028..1087)
        const int q = t - 65;              // 0..14
#pragma unroll 1
        for (int i = 0; i < FSEG; i++) {
            *(unsigned int*)(Ab + base + (size_t)(1 + s * FSEG + i) * rowStride +
                             1028 + 4 * q) = 0u;
        }
    }
}

// ---------------------------------------------------------------------------
// kG: fp16 mma.sync GEMM, BK=32, 5-stage cp.async pipeline, K = 1088.
// Chunks 0..16 read compact-A rows (f), chunks 17..33 read rows (f-1);
// the (-1)^k sign lives in B rows 544..1087. grid = (2, 512).
// Fused L2 normalization via release/acquire finisher (proven protocol).
// ---------------------------------------------------------------------------
#define LDA_S 40
#define LDB_S 136
#define AS_BYTES (128 * LDA_S * 2)
#define BS_BYTES (32 * LDB_S * 2)
#define NSTAGE   5
#define SMEM_KG  (NSTAGE * (AS_BYTES + BS_BYTES))

__device__ __forceinline__ void cpa16(unsigned int s, const void* g) {
    asm volatile("cp.async.cg.shared.global [%0],[%1],16;" :: "r"(s), "l"(g));
}
__device__ __forceinline__ void ldm4(unsigned int& r0, unsigned int& r1,
                                     unsigned int& r2, unsigned int& r3, unsigned int a) {
    asm volatile("ldmatrix.sync.aligned.m8n8.x4.shared.b16 {%0,%1,%2,%3},[%4];"
                 : "=r"(r0), "=r"(r1), "=r"(r2), "=r"(r3) : "r"(a));
}
__device__ __forceinline__ void ldm4t(unsigned int& r0, unsigned int& r1,
                                      unsigned int& r2, unsigned int& r3, unsigned int a) {
    asm volatile("ldmatrix.sync.aligned.m8n8.x4.trans.shared.b16 {%0,%1,%2,%3},[%4];"
                 : "=r"(r0), "=r"(r1), "=r"(r2), "=r"(r3) : "r"(a));
}
__device__ __forceinline__ void mma16816(float* c, const unsigned int* a, const unsigned int* b) {
    asm volatile("mma.sync.aligned.m16n8k16.row.col.f32.f16.f16.f32 "
                 "{%0,%1,%2,%3},{%4,%5,%6,%7},{%8,%9},{%0,%1,%2,%3};"
                 : "+f"(c[0]), "+f"(c[1]), "+f"(c[2]), "+f"(c[3])
                 : "r"(a[0]), "r"(a[1]), "r"(a[2]), "r"(a[3]), "r"(b[0]), "r"(b[1]));
}

__global__ void __launch_bounds__(256, 2) kG(float* __restrict__ out) {
    extern __shared__ __align__(16) __half dsm[];
    __shared__ float red[8];
    __shared__ unsigned s_flag;
    __shared__ float s_inv;

    const int tid   = threadIdx.x;
    const int lane  = tid & 31;
    const int wid   = tid >> 5;
    const int warpM = wid >> 2;
    const int warpN = wid & 3;
    const int mBase = blockIdx.y * 128;                   // output row panel
    const int nBase = blockIdx.x * 128;                   // N half
    const size_t aBase = (size_t)blockIdx.y * ROWSB * AKC;  // compact-A batch base

    const unsigned int base = (unsigned int)__cvta_generic_to_shared(dsm);
#define SA_STAGE(i) (base + (unsigned)(i) * AS_BYTES)
#define SB_STAGE(i) (base + (unsigned)NSTAGE * AS_BYTES + (unsigned)(i) * BS_BYTES)

    const int aRow = tid >> 2, aOff = (tid & 3) * 8;
    const int bRow = tid >> 4, bOff = (tid & 15) * 8;

    const __half* A = g_A;
    const __half* B = g_B;

    float c[4][4][4];
#pragma unroll
    for (int i = 0; i < 4; i++)
#pragma unroll
        for (int j = 0; j < 4; j++)
#pragma unroll
            for (int q = 0; q < 4; q++) c[i][j][q] = 0.f;

    const int lrow  = (lane & 7) + ((lane >> 3) & 1) * 8;
    const int lcol8 = (lane >> 4) * 8;

#define PREFETCH(cIdx, st)                                                            \
    {                                                                                 \
        const int c_ = (cIdx);                                                        \
        const int cc = (c_ < 17) ? c_ : (c_ - 17);                                    \
        const int ro = (c_ < 17) ? 1 : 0;   /* current: row f+1; shifted: row f */    \
        const int bR = c_ * 32;                                                       \
        const unsigned int sa = SA_STAGE(st);                                         \
        const unsigned int sb = SB_STAGE(st);                                         \
        const __half* ap = A + aBase + (size_t)(aRow + ro) * AKC + cc * 32 + aOff;    \
        cpa16(sa + (unsigned)(aRow * LDA_S + aOff) * 2, ap);                          \
        cpa16(sa + (unsigned)((aRow + 64) * LDA_S + aOff) * 2, ap + 64 * AKC);        \
        cpa16(sb + (unsigned)(bRow * LDB_S + bOff) * 2,                               \
              B + (size_t)(bR + bRow) * 256 + nBase + bOff);                          \
        cpa16(sb + (unsigned)((bRow + 16) * LDB_S + bOff) * 2,                        \
              B + (size_t)(bR + bRow + 16) * 256 + nBase + bOff);                     \
        asm volatile("cp.async.commit_group;");                                       \
    }

    PREFETCH(0, 0)
    PREFETCH(1, 1)
    PREFETCH(2, 2)
    PREFETCH(3, 3)

    int stg = 0;
    for (int ch = 0; ch < NCHUNK; ch++) {
        if (ch + 4 < NCHUNK) {
            asm volatile("cp.async.wait_group 3;");
        } else {
            asm volatile("cp.async.wait_group 0;");
        }
        __syncthreads();
        if (ch + 4 < NCHUNK) {
            int pstg = stg + 4; if (pstg >= NSTAGE) pstg -= NSTAGE;
            PREFETCH(ch + 4, pstg)
        }

        const unsigned int sAcur = SA_STAGE(stg);
        const unsigned int sBcur = SB_STAGE(stg);
#pragma unroll
        for (int kk = 0; kk < 32; kk += 16) {
            unsigned int af[4][4];
#pragma unroll
            for (int mi = 0; mi < 4; mi++) {
                const unsigned int addr = sAcur +
                    (unsigned)((warpM * 64 + mi * 16 + lrow) * LDA_S + kk + lcol8) * 2;
                ldm4(af[mi][0], af[mi][1], af[mi][2], af[mi][3], addr);
            }
            unsigned int bf[4][2];
#pragma unroll
            for (int nj = 0; nj < 2; nj++) {
                const unsigned int addr = sBcur +
                    (unsigned)((kk + lrow) * LDB_S + warpN * 32 + nj * 16 + lcol8) * 2;
                unsigned int r0, r1, r2, r3;
                ldm4t(r0, r1, r2, r3, addr);
                bf[nj * 2][0] = r0; bf[nj * 2][1] = r1;
                bf[nj * 2 + 1][0] = r2; bf[nj * 2 + 1][1] = r3;
            }
#pragma unroll
            for (int mi = 0; mi < 4; mi++)
#pragma unroll
                for (int nf = 0; nf < 4; nf++)
                    mma16816(c[mi][nf], af[mi], bf[nf]);
        }
        if (++stg == NSTAGE) stg = 0;
    }

    // ---- store unnormalized + partial sum of squares ----
    float ss = 0.f;
#pragma unroll
    for (int mi = 0; mi < 4; mi++) {
#pragma unroll
        for (int nf = 0; nf < 4; nf++) {
            const int r = mBase + warpM * 64 + mi * 16 + (lane >> 2);
            const int n = nBase + warpN * 32 + nf * 8 + (lane & 3) * 2;
            float2* p0 = (float2*)(out + (size_t)r * 256 + n);
            float2* p1 = (float2*)(out + (size_t)(r + 8) * 256 + n);
            *p0 = make_float2(c[mi][nf][0], c[mi][nf][1]);
            *p1 = make_float2(c[mi][nf][2], c[mi][nf][3]);
#pragma unroll
            for (int q = 0; q < 4; q++) ss = fmaf(c[mi][nf][q], c[mi][nf][q], ss);
        }
    }
#pragma unroll
    for (int o = 16; o > 0; o >>= 1) ss += __shfl_xor_sync(0xffffffffu, ss, o);
    if (lane == 0) red[wid] = ss;

    // release: make this CTA's stores visible before signaling
    __threadfence();
    __syncthreads();

    if (tid == 0) {
        float tot = 0.f;
#pragma unroll
        for (int i = 0; i < 8; i++) tot += red[i];
        atomicAdd(&g_ss[blockIdx.y], tot);
        __threadfence();                                  // order ss-add before cnt-add
        const unsigned old = atomicAdd(&g_cnt[blockIdx.y], 1u);
        s_flag = old;                                     // 1 -> we are the finisher
        if (old == 1u) {
            __threadfence();                              // acquire
            s_inv = 1.f / (sqrtf(g_ss[blockIdx.y]) + 1e-8f);
        }
    }
    __syncthreads();

    if (s_flag == 1u) {
        const float inv = s_inv;
        // own half: rescale from still-live registers (no global re-read)
#pragma unroll
        for (int mi = 0; mi < 4; mi++) {
#pragma unroll
            for (int nf = 0; nf < 4; nf++) {
                const int r = mBase + warpM * 64 + mi * 16 + (lane >> 2);
                const int n = nBase + warpN * 32 + nf * 8 + (lane & 3) * 2;
                float2* p0 = (float2*)(out + (size_t)r * 256 + n);
                float2* p1 = (float2*)(out + (size_t)(r + 8) * 256 + n);
                *p0 = make_float2(c[mi][nf][0] * inv, c[mi][nf][1] * inv);
                *p1 = make_float2(c[mi][nf][2] * inv, c[mi][nf][3] * inv);
            }
        }
        // partner half: read-scale-write (L2-hot)
        const int pbase = nBase ^ 128;
#pragma unroll 4
        for (int i = tid; i < 128 * 32; i += 256) {
            const int row = i >> 5, c4 = i & 31;
            float4* p = (float4*)(out + (size_t)(mBase + row) * 256 + pbase) + c4;
            float4 v = *p;
            v.x *= inv; v.y *= inv; v.z *= inv; v.w *= inv;
            *p = v;
        }
    }
#undef PREFETCH
#undef SA_STAGE
#undef SB_STAGE
}

extern "C" void kernel_launch(void* const* d_in, const int* in_sizes, int n_in,
                              void* d_out, int out_size) {
    const float* sel   = (const float*)d_in[0];
    const float* items = (const float*)d_in[1];
    if (n_in >= 2 && in_sizes[0] == 512 * 771) {
        items = (const float*)d_in[0];
        sel   = (const float*)d_in[1];
    }
    float* out = (float*)d_out;

    static bool attr_set = false;
    if (!attr_set) {
        cudaFuncSetAttribute(kG, cudaFuncAttributeMaxDynamicSharedMemorySize, SMEM_KG);
        attr_set = true;
    }

    kP1a<<<dim3(NB / BPB, NSPLIT + 1), 288>>>(sel, items);
    kP2<<<dim3(NB, NSEGQ), 96>>>();
    kG<<<dim3(2, NB), 256, SMEM_KG>>>(out);
}